// round 13
// baseline (speedup 1.0000x reference)
#include <cuda_runtime.h>
#include <cuda_bf16.h>
#include <math.h>

#define BB 4
#define TT 512
#define SS 1536
#define SDIM 64
#define ADIM 32
#define HDIM 512
#define HPH 256
#define NH 8
#define DH 64
#define NBLK 6
#define DFFH 1024
#define DFF 2048
#define MROWS (BB*SS)

enum { EP_BIAS = 0, EP_GELU_SPLIT = 2, EP_BIAS_SPLIT = 3 };

// ---------------- scratch ----------------
__device__ float g_h  [MROWS * HDIM];
__device__ float g_v  [MROWS * HDIM];
__device__ float g_p0 [MROWS * HDIM];
__device__ float g_p1 [MROWS * HDIM];
__device__ float g_p2 [MROWS * HDIM];
__device__ float g_p3 [MROWS * HDIM];
__device__ float g_ln1[MROWS * HDIM];

__device__ uint2 g_hs  [MROWS * HPH];
__device__ uint2 g_qs  [MROWS * HPH];
__device__ uint2 g_ks  [MROWS * HPH];
__device__ uint2 g_ctxs[MROWS * HPH];
__device__ uint2 g_ln1s[MROWS * HPH];
__device__ uint2 g_mlps[MROWS * DFFH];

// transposed split weights: [blk][N][K/2] uint2
#define WQ0 0
#define WK0 786432
#define WV0 1572864
#define WO0 2359296
#define W10 3145728
#define W20 6291456
__device__ uint2 g_ws[9437184];

// ---------------- bf16 split helpers ----------------
__device__ __forceinline__ uint2 split2bf(float x0, float x1) {
    __nv_bfloat162 h = __floats2bfloat162_rn(x0, x1);
    float r0 = x0 - __bfloat162float(h.x);
    float r1 = x1 - __bfloat162float(h.y);
    __nv_bfloat162 l = __floats2bfloat162_rn(r0, r1);
    uint2 out;
    out.x = *reinterpret_cast<unsigned*>(&h);
    out.y = *reinterpret_cast<unsigned*>(&l);
    return out;
}

__device__ __forceinline__ void mma16(float c[4],
    unsigned a0, unsigned a1, unsigned a2, unsigned a3,
    unsigned b0, unsigned b1)
{
    asm volatile(
      "mma.sync.aligned.m16n8k16.row.col.f32.bf16.bf16.f32 "
      "{%0,%1,%2,%3},{%4,%5,%6,%7},{%8,%9},{%0,%1,%2,%3};"
      : "+f"(c[0]), "+f"(c[1]), "+f"(c[2]), "+f"(c[3])
      : "r"(a0), "r"(a1), "r"(a2), "r"(a3), "r"(b0), "r"(b1));
}

__device__ __forceinline__ void cpa16(void* s, const void* g) {
    unsigned a = (unsigned)__cvta_generic_to_shared(s);
    asm volatile("cp.async.cg.shared.global [%0], [%1], 16;" :: "r"(a), "l"(g));
}
#define CP_COMMIT() asm volatile("cp.async.commit_group;")
#define CP_WAIT0()  asm volatile("cp.async.wait_group 0;")

// ---------------- reductions ----------------
__device__ __forceinline__ float blockReduceSum(float v, float* sm) {
    int lane = threadIdx.x & 31, wid = threadIdx.x >> 5;
    #pragma unroll
    for (int o = 16; o; o >>= 1) v += __shfl_down_sync(0xffffffffu, v, o);
    if (lane == 0) sm[wid] = v;
    __syncthreads();
    float r = 0.f;
    if (wid == 0) {
        r = (lane < 8) ? sm[lane] : 0.f;
        #pragma unroll
        for (int o = 4; o; o >>= 1) r += __shfl_down_sync(0xffffffffu, r, o);
        if (lane == 0) sm[0] = r;
    }
    __syncthreads();
    r = sm[0];
    __syncthreads();
    return r;
}

// -------- weight transpose+split: W[K][N] -> WT[N][K/2] (hi,lo uint2) ---------
__global__ __launch_bounds__(256) void wtsplit_kernel(
    const float* __restrict__ src, uint2* __restrict__ dst, int K, int N)
{
    __shared__ float sm[32][129];
    int k0 = blockIdx.x * 32, n0 = blockIdx.y * 128;
    int KW = K >> 1;
    const float* S = src + (size_t)blockIdx.z * K * N;
    uint2* D = dst + (size_t)blockIdx.z * N * KW;
    int tid = threadIdx.x;
    #pragma unroll
    for (int i = 0; i < 16; i++) {
        int id = tid + 256*i, r = id >> 7, c = id & 127;
        sm[r][c] = S[(size_t)(k0 + r)*N + n0 + c];
    }
    __syncthreads();
    #pragma unroll
    for (int i = 0; i < 8; i++) {
        int id = tid + 256*i, kpl = id & 15, nn = id >> 4;
        D[(size_t)(n0 + nn)*KW + (k0 >> 1) + kpl] =
            split2bf(sm[2*kpl][nn], sm[2*kpl + 1][nn]);
    }
}

// ---------------- embedding + eLN ----------------
__global__ __launch_bounds__(256) void embed_kernel(
    const int* __restrict__ timesteps, const float* __restrict__ s0,
    const float* __restrict__ s1, const float* __restrict__ act,
    const float* __restrict__ temb,
    const float* __restrict__ Ws, const float* __restrict__ bs,
    const float* __restrict__ Wa, const float* __restrict__ ba,
    const float* __restrict__ eg, const float* __restrict__ eb,
    float* __restrict__ out, uint2* __restrict__ outs)
{
    int s = blockIdx.x;
    int b = s / SS, sr = s % SS;
    int t = sr / 3, r = sr % 3;

    __shared__ float sIn[SDIM];
    __shared__ float red[32];

    const float* inp; const float* W; const float* bias; int Kin;
    if (r == 0)      { inp = s0  + (size_t)(b*TT + t)*SDIM; W = Ws; bias = bs; Kin = SDIM; }
    else if (r == 1) { inp = s1  + (size_t)(b*TT + t)*SDIM; W = Ws; bias = bs; Kin = SDIM; }
    else             { inp = act + (size_t)(b*TT + t)*ADIM; W = Wa; bias = ba; Kin = ADIM; }

    int tid = threadIdx.x;
    if (tid < Kin) sIn[tid] = inp[tid];
    __syncthreads();

    int tsv = timesteps[b*TT + t];
    const float* te = temb + (size_t)tsv * HDIM;

    int c0 = 2*tid;
    float a0 = bias[c0] + te[c0], a1 = bias[c0+1] + te[c0+1];
    for (int k = 0; k < Kin; k++) {
        float x = sIn[k];
        a0 = fmaf(x, W[(size_t)k*HDIM + c0],     a0);
        a1 = fmaf(x, W[(size_t)k*HDIM + c0 + 1], a1);
    }
    float sum = blockReduceSum(a0 + a1, red);
    float m = sum * (1.0f / HDIM);
    float d0 = a0 - m, d1 = a1 - m;
    float ssq = blockReduceSum(d0*d0 + d1*d1, red);
    float rstd = rsqrtf(ssq * (1.0f / HDIM) + 1e-5f);
    float o0 = d0 * rstd * eg[c0]     + eb[c0];
    float o1 = d1 * rstd * eg[c0 + 1] + eb[c0 + 1];
    *(float2*)(out + (size_t)s*HDIM + c0) = make_float2(o0, o1);
    outs[(size_t)s*HPH + tid] = split2bf(o0, o1);
}

// ====== GEMM: 128 threads, tile 128x128, warp grid 2x2 (64x64), bf16x3 ========
// A: [M][K/2] uint2. B (weights): [N][K/2] uint2 (transposed). Both smem tiles
// [row][kp] with pad 20 -> conflict-free fragment loads. 2-stage cp.async.
#define APAD 20
#define TSTG (128*APAD)
#define SMG  (2*2*TSTG*(int)sizeof(uint2))   // 81920 B

__device__ __forceinline__ void gemm_core(
    const uint2* __restrict__ A, const uint2* __restrict__ B,
    float acc[4][8][4], int m0, int n0, int KW, int kwb, int Tit, char* smraw)
{
    uint2* Sm = (uint2*)smraw;
    const int tid  = threadIdx.x, lane = tid & 31, warp = tid >> 5;
    const int g    = lane >> 2,  tg   = lane & 3;
    const int wm0  = (warp >> 1) * 64, wn0 = (warp & 1) * 64;

    auto fill = [&](int t, int s) {
        uint2* St = Sm + s*2*TSTG;
        int kw0 = kwb + t * 16;
        #pragma unroll
        for (int i = 0; i < 8; i++) {
            int id = tid + 128*i, r = id >> 3, c = (id & 7) * 2;
            cpa16(St + r*APAD + c,        A + (size_t)(m0 + r)*KW + kw0 + c);
            cpa16(St + TSTG + r*APAD + c, B + (size_t)(n0 + r)*KW + kw0 + c);
        }
        CP_COMMIT();
    };

    fill(0, 0);

    for (int t = 0; t < Tit; t++) {
        const int s = t & 1;
        CP_WAIT0();
        __syncthreads();
        if (t + 1 < Tit) fill(t + 1, s ^ 1);

        const uint2* As_ = Sm + s*2*TSTG;
        const uint2* Bs_ = As_ + TSTG;
        #pragma unroll
        for (int ks = 0; ks < 2; ks++) {
            const int kb = ks * 8;
            uint2 bf[8][2];
            #pragma unroll
            for (int tn = 0; tn < 8; tn++) {
                int n = wn0 + tn*8 + g;
                bf[tn][0] = Bs_[n*APAD + kb + tg];
                bf[tn][1] = Bs_[n*APAD + kb + tg + 4];
            }
            #pragma unroll
            for (int tm = 0; tm < 4; tm++) {
                int m = wm0 + tm*16 + g;
                uint2 a0 = As_[m*APAD + kb + tg];
                uint2 a1 = As_[(m+8)*APAD + kb + tg];
                uint2 a2 = As_[m*APAD + kb + tg + 4];
                uint2 a3 = As_[(m+8)*APAD + kb + tg + 4];
                #pragma unroll
                for (int tn = 0; tn < 8; tn++) {
                    mma16(acc[tm][tn], a0.x,a1.x,a2.x,a3.x, bf[tn][0].x, bf[tn][1].x);
                    mma16(acc[tm][tn], a0.y,a1.y,a2.y,a3.y, bf[tn][0].x, bf[tn][1].x);
                    mma16(acc[tm][tn], a0.x,a1.x,a2.x,a3.x, bf[tn][0].y, bf[tn][1].y);
                }
            }
        }
    }
}

__device__ __forceinline__ void gemm_body64(
    const uint2* __restrict__ A, const uint2* __restrict__ B,
    const float* __restrict__ bias,
    float* __restrict__ C, uint2* __restrict__ Cs,
    int N, int K, int ep, float scl, char* smraw)
{
    const int lane = threadIdx.x & 31, warp = threadIdx.x >> 5;
    const int g    = lane >> 2,  tg   = lane & 3;
    const int wm0  = (warp >> 1) * 64, wn0 = (warp & 1) * 64;
    const int m0   = blockIdx.y * 128, n0 = blockIdx.x * 128;

    float acc[4][8][4];
    #pragma unroll
    for (int i = 0; i < 4; i++)
        #pragma unroll
        for (int j = 0; j < 8; j++)
            #pragma unroll
            for (int l = 0; l < 4; l++) acc[i][j][l] = 0.f;

    gemm_core(A, B, acc, m0, n0, K >> 1, 0, K / 32, smraw);

    #pragma unroll
    for (int tm = 0; tm < 4; tm++) {
        #pragma unroll
        for (int tn = 0; tn < 8; tn++) {
            int row = m0 + wm0 + tm*16 + g;
            int col = n0 + wn0 + tn*8 + tg*2;
            float b0v = bias[col], b1v = bias[col+1];
            float v00 = acc[tm][tn][0] + b0v, v01 = acc[tm][tn][1] + b1v;
            float v10 = acc[tm][tn][2] + b0v, v11 = acc[tm][tn][3] + b1v;
            if (ep == EP_BIAS) {
                *(float2*)(C + (size_t)row*N + col)     = make_float2(v00, v01);
                *(float2*)(C + (size_t)(row+8)*N + col) = make_float2(v10, v11);
            } else {
                if (ep == EP_GELU_SPLIT) {
                    v00 = 0.5f*v00*(1.0f + erff(v00*0.70710678118654752f));
                    v01 = 0.5f*v01*(1.0f + erff(v01*0.70710678118654752f));
                    v10 = 0.5f*v10*(1.0f + erff(v10*0.70710678118654752f));
                    v11 = 0.5f*v11*(1.0f + erff(v11*0.70710678118654752f));
                } else {
                    v00 *= scl; v01 *= scl; v10 *= scl; v11 *= scl;
                }
                Cs[(size_t)row*(N>>1)     + (col>>1)] = split2bf(v00, v01);
                Cs[(size_t)(row+8)*(N>>1) + (col>>1)] = split2bf(v10, v11);
            }
        }
    }
}

__global__ __launch_bounds__(128, 2) void tgemm_kernel(
    const uint2* __restrict__ A, const uint2* __restrict__ B,
    const float* __restrict__ bias,
    float* __restrict__ C, uint2* __restrict__ Cs,
    int N, int K, int ep)
{
    extern __shared__ char smraw[];
    gemm_body64(A, B, bias, C, Cs, N, K, ep, 1.0f, smraw);
}

__global__ __launch_bounds__(128, 2) void qkv_kernel(
    const uint2* __restrict__ hs,
    const uint2* __restrict__ wq, const uint2* __restrict__ wk, const uint2* __restrict__ wv,
    const float* __restrict__ bq, const float* __restrict__ bk, const float* __restrict__ bv,
    uint2* __restrict__ qs, uint2* __restrict__ ks, float* __restrict__ v)
{
    extern __shared__ char smraw[];
    if (blockIdx.z == 0)
        gemm_body64(hs, wq, bq, nullptr, qs, HDIM, HDIM, EP_BIAS_SPLIT, 0.125f, smraw);
    else if (blockIdx.z == 1)
        gemm_body64(hs, wk, bk, nullptr, ks, HDIM, HDIM, EP_BIAS_SPLIT, 1.0f, smraw);
    else
        gemm_body64(hs, wv, bv, v, nullptr, HDIM, HDIM, EP_BIAS, 1.0f, smraw);
}

// ---------- split-K (4-way) GEMM: raw fp32 partials -------------------------
__global__ __launch_bounds__(128, 2) void tgemm_sk_kernel(
    const uint2* __restrict__ A, const uint2* __restrict__ B,
    float* __restrict__ P0, float* __restrict__ P1,
    float* __restrict__ P2, float* __restrict__ P3,
    int N, int K)
{
    extern __shared__ char smraw[];
    const int lane = threadIdx.x & 31, warp = threadIdx.x >> 5;
    const int g    = lane >> 2,  tg   = lane & 3;
    const int wm0  = (warp >> 1) * 64, wn0 = (warp & 1) * 64;
    const int m0   = blockIdx.y * 128, n0 = blockIdx.x * 128;
    const int z    = blockIdx.z;
    const int KW   = K >> 1;
    float* P = (z == 0) ? P0 : (z == 1) ? P1 : (z == 2) ? P2 : P3;

    float acc[4][8][4];
    #pragma unroll
    for (int i = 0; i < 4; i++)
        #pragma unroll
        for (int j = 0; j < 8; j++)
            #pragma unroll
            for (int l = 0; l < 4; l++) acc[i][j][l] = 0.f;

    gemm_core(A, B, acc, m0, n0, KW, z * (KW >> 2), (K / 4) / 32, smraw);

    #pragma unroll
    for (int tm = 0; tm < 4; tm++)
        #pragma unroll
        for (int tn = 0; tn < 8; tn++) {
            int row = m0 + wm0 + tm*16 + g;
            int col = n0 + wn0 + tn*8 + tg*2;
            *(float2*)(P + (size_t)row*N + col)     = make_float2(acc[tm][tn][0], acc[tm][tn][1]);
            *(float2*)(P + (size_t)(row+8)*N + col) = make_float2(acc[tm][tn][2], acc[tm][tn][3]);
        }
}

// ================= flash attention =============================================
#define FLASH_KPAD 132
#define FLASH_VPAD 68
#define FLASH_SMEM ((32*FLASH_KPAD + 64*FLASH_VPAD) * (int)sizeof(uint2))

__global__ __launch_bounds__(256) void flash_kernel(
    const uint2* __restrict__ q, const uint2* __restrict__ k,
    const float* __restrict__ v, uint2* __restrict__ ctxs)
{
    extern __shared__ uint2 dsmem[];
    uint2 (*Ks)[FLASH_KPAD] = reinterpret_cast<uint2(*)[FLASH_KPAD]>(dsmem);
    uint2 (*Vs)[FLASH_VPAD] = reinterpret_cast<uint2(*)[FLASH_VPAD]>(dsmem + 32*FLASH_KPAD);

    const int it = (int)(gridDim.x - 1 - blockIdx.x);
    const int bh = blockIdx.y, b = bh >> 3, h = bh & 7;
    const uint2* qb = q + (size_t)b*SS*HPH + h*32;
    const uint2* kb = k + (size_t)b*SS*HPH + h*32;
    const float* vb = v + (size_t)b*SS*HDIM + h*DH;
    uint2* cb       = ctxs + (size_t)b*SS*HPH + h*32;

    const int tid  = threadIdx.x, lane = tid & 31, warp = tid >> 5;
    const int g    = lane >> 2,  tg   = lane & 3;
    const int i0   = it * 128;
    const int rowg = i0 + warp*16 + g;

    uint2 qf[4][4];
    {
        const uint2* qrg = qb + (size_t)rowg*HPH;
        const uint2* qr8 = qrg + 8*HPH;
        #pragma unroll
        for (int kk = 0; kk < 4; kk++) {
            qf[kk][0] = qrg[kk*8 + tg];
            qf[kk][1] = qr8[kk*8 + tg];
            qf[kk][2] = qrg[kk*8 + tg + 4];
            qf[kk][3] = qr8[kk*8 + tg + 4];
        }
    }

    float m0 = -1e30f, m1 = -1e30f, l0 = 0.f, l1 = 0.f;
    float o[8][4];
    #pragma unroll
    for (int nf = 0; nf < 8; nf++)
        #pragma unroll
        for (int l = 0; l < 4; l++) o[nf][l] = 0.f;

    const int kjr = tid >> 1, kcb = (tid & 1)*16;
    const int vjp = tid >> 2, vcb = (tid & 3)*16;

    for (int jt = 0; jt <= it; jt++) {
        const int j0 = jt * 128;
        {
            const uint2* krow = kb + (size_t)(j0 + kjr)*HPH + kcb;
            #pragma unroll
            for (int u = 0; u < 8; u++) {
                uint4 f = ((const uint4*)krow)[u];
                Ks[kcb + 2*u][kjr]     = make_uint2(f.x, f.y);
                Ks[kcb + 2*u + 1][kjr] = make_uint2(f.z, f.w);
            }
        }
        {
            const float* vr0 = vb + (size_t)(j0 + 2*vjp)*HDIM + vcb;
            const float* vr1 = vr0 + HDIM;
            #pragma unroll
            for (int u = 0; u < 4; u++) {
                float4 f0 = *(const float4*)(vr0 + u*4);
                float4 f1 = *(const float4*)(vr1 + u*4);
                Vs[vjp][vcb + u*4 + 0] = split2bf(f0.x, f1.x);
                Vs[vjp][vcb + u*4 + 1] = split2bf(f0.y, f1.y);
                Vs[vjp][vcb + u*4 + 2] = split2bf(f0.z, f1.z);
                Vs[vjp][vcb + u*4 + 3] = split2bf(f0.w, f1.w);
            }
        }
        __syncthreads();

        float s[16][4];
        #pragma unroll
        for (int jf = 0; jf < 16; jf++)
            #pragma unroll
            for (int l = 0; l < 4; l++) s[jf][l] = 0.f;

        #pragma unroll
        for (int kk = 0; kk < 4; kk++) {
            uint2 a0 = qf[kk][0], a1 = qf[kk][1], a2 = qf[kk][2], a3 = qf[kk][3];
            #pragma unroll
            for (int jf = 0; jf < 16; jf++) {
                uint2 b0 = Ks[kk*8 + tg][jf*8 + g];
                uint2 b1 = Ks[kk*8 + tg + 4][jf*8 + g];
                mma16(s[jf], a0.x,a1.x,a2.x,a3.x, b0.x, b1.x);
                mma16(s[jf], a0.y,a1.y,a2.y,a3.y, b0.x, b1.x);
                mma16(s[jf], a0.x,a1.x,a2.x,a3.x, b0.y, b1.y);
            }
        }

        if (jt == it) {
            const int r0 = warp*16 + g, r1 = r0 + 8;
            #pragma unroll
            for (int jf = 0; jf < 16; jf++) {
                int c0 = jf*8 + 2*tg;
                if (c0     > r0) s[jf][0] = -1e30f;
                if (c0 + 1 > r0) s[jf][1] = -1e30f;
                if (c0     > r1) s[jf][2] = -1e30f;
                if (c0 + 1 > r1) s[jf][3] = -1e30f;
            }
        }

        float tm0 = -1e30f, tm1 = -1e30f;
        #pragma unroll
        for (int jf = 0; jf < 16; jf++) {
            tm0 = fmaxf(tm0, fmaxf(s[jf][0], s[jf][1]));
            tm1 = fmaxf(tm1, fmaxf(s[jf][2], s[jf][3]));
        }
        tm0 = fmaxf(tm0, __shfl_xor_sync(0xffffffffu, tm0, 1));
        tm0 = fmaxf(tm0, __shfl_xor_sync(0xffffffffu, tm0, 2));
        tm1 = fmaxf(tm1, __shfl_xor_sync(0xffffffffu, tm1, 1));
        tm1 = fmaxf(tm1, __shfl_xor_sync(0xffffffffu, tm1, 2));

        float nm0 = fmaxf(m0, tm0), nm1 = fmaxf(m1, tm1);
        float al0 = __expf(m0 - nm0), al1 = __expf(m1 - nm1);
        m0 = nm0; m1 = nm1;

        float rs0 = 0.f, rs1 = 0.f;
        #pragma unroll
        for (int jf = 0; jf < 16; jf++) {
            s[jf][0] = __expf(s[jf][0] - nm0);
            s[jf][1] = __expf(s[jf][1] - nm0);
            s[jf][2] = __expf(s[jf][2] - nm1);
            s[jf][3] = __expf(s[jf][3] - nm1);
            rs0 += s[jf][0] + s[jf][1];
            rs1 += s[jf][2] + s[jf][3];
        }
        rs0 += __shfl_xor_sync(0xffffffffu, rs0, 1);
        rs0 += __shfl_xor_sync(0xffffffffu, rs0, 2);
        rs1 += __shfl_xor_sync(0xffffffffu, rs1, 1);
        rs1 += __shfl_xor_sync(0xffffffffu, rs1, 2);
        l0 = l0*al0 + rs0;
        l1 = l1*al1 + rs1;

        #pragma unroll
        for (int nf = 0; nf < 8; nf++) {
            o[nf][0] *= al0; o[nf][1] *= al0;
            o[nf][2] *= al1; o[nf][3] *= al1;
        }

        #pragma unroll
        for (int kk = 0; kk < 8; kk++) {
            uint2 A0 = split2bf(s[2*kk][0],   s[2*kk][1]);
            uint2 A1 = split2bf(s[2*kk][2],   s[2*kk][3]);
            uint2 A2 = split2bf(s[2*kk+1][0], s[2*kk+1][1]);
            uint2 A3 = split2bf(s[2*kk+1][2], s[2*kk+1][3]);
            #pragma unroll
            for (int nf = 0; nf < 8; nf++) {
                uint2 b0 = Vs[kk*8 + tg][nf*8 + g];
                uint2 b1 = Vs[kk*8 + tg + 4][nf*8 + g];
                mma16(o[nf], A0.x,A1.x,A2.x,A3.x, b0.x, b1.x);
                mma16(o[nf], A0.y,A1.y,A2.y,A3.y, b0.x, b1.x);
                mma16(o[nf], A0.x,A1.x,A2.x,A3.x, b0.y, b1.y);
            }
        }
        __syncthreads();
    }

    float inv0 = 1.0f / l0, inv1 = 1.0f / l1;
    uint2* crow0 = cb + (size_t)rowg*HPH;
    uint2* crow1 = crow0 + 8*HPH;
    #pragma unroll
    for (int nf = 0; nf < 8; nf++) {
        crow0[nf*4 + tg] = split2bf(o[nf][0]*inv0, o[nf][1]*inv0);
        crow1[nf*4 + tg] = split2bf(o[nf][2]*inv1, o[nf][3]*inv1);
    }
}

// ---- layernorm over (p0+p1+p2+p3 + bias + res): warp-per-row -----------------
__global__ __launch_bounds__(256) void ln_sum_kernel(
    const float* __restrict__ p0, const float* __restrict__ p1,
    const float* __restrict__ p2, const float* __restrict__ p3,
    const float* __restrict__ bias, const float* __restrict__ res,
    const float* __restrict__ g, const float* __restrict__ b,
    float* __restrict__ out, uint2* __restrict__ outs)
{
    int row  = blockIdx.x * 8 + (threadIdx.x >> 5);
    int lane = threadIdx.x & 31;
    size_t ro = (size_t)row * HDIM;

    float4 xv[4];
    float sum = 0.f;
    #pragma unroll
    for (int i = 0; i < 4; i++) {
        int c = lane*4 + i*128;
        float4 a = *(const float4*)(p0 + ro + c);
        float4 d = *(const float4*)(p1 + ro + c);
        float4 e = *(const float4*)(p2 + ro + c);
        float4 f = *(const float4*)(p3 + ro + c);
        float4 bb = *(const float4*)(bias + c);
        float4 rr = *(const float4*)(res + ro + c);
        xv[i].x = ((a.x + d.x) + (e.x + f.x)) + (bb.x + rr.x);
        xv[i].y = ((a.y + d.y) + (e.y + f.y)) + (bb.y + rr.y);
        xv[i].z = ((a.z + d.z) + (e.z + f.z)) + (bb.z + rr.z);
        xv[i].w = ((a.w + d.w) + (e.w + f.w)) + (bb.w + rr.w);
        sum += (xv[i].x + xv[i].y) + (xv[i].z + xv[i].w);
    }
    #pragma unroll
    for (int o = 16; o; o >>= 1) sum += __shfl_xor_sync(0xffffffffu, sum, o);
    float m = sum * (1.0f / HDIM);

    float ssq = 0.f;
    #pragma unroll
    for (int i = 0; i < 4; i++) {
        xv[i].x -= m; xv[i].y -= m; xv[i].z -= m; xv[i].w -= m;
        ssq += xv[i].x*xv[i].x + xv[i].y*xv[i].y + xv[i].z*xv[i].z + xv[i].w*xv[i].w;
    }
    #pragma unroll
    for (int o = 16; o; o >>= 1) ssq += __shfl_xor_sync(0xffffffffu, ssq, o);
    float rstd = rsqrtf(ssq * (1.0f / HDIM) + 1e-5f);

    float* outr = out + ro;
    uint2* outsr = outs + (size_t)row * HPH;
    #pragma unroll
    for (int i = 0; i < 4; i++) {
        int c = lane*4 + i*128;
        float4 gv = *(const float4*)(g + c);
        float4 bv = *(const float4*)(b + c);
        float4 ov;
        ov.x = xv[i].x * rstd * gv.x + bv.x;
        ov.y = xv[i].y * rstd * gv.y + bv.y;
        ov.z = xv[i].z * rstd * gv.z + bv.z;
        ov.w = xv[i].w * rstd * gv.w + bv.w;
        *(float4*)(outr + c) = ov;
        outsr[(c >> 1)    ] = split2bf(ov.x, ov.y);
        outsr[(c >> 1) + 1] = split2bf(ov.z, ov.w);
    }
}

// ---------------- final projection ----------------
__global__ __launch_bounds__(256) void final_kernel(
    const float* __restrict__ h, const float* __restrict__ Wp,
    const float* __restrict__ bp, float* __restrict__ out)
{
    int bt = blockIdx.x;
    int b = bt / TT, t = bt % TT;
    const float* row = h + ((size_t)b*SS + 3*t + 1) * HDIM;
    __shared__ float sRow[HDIM];
    __shared__ float part[8][ADIM];
    int tid = threadIdx.x;
    sRow[tid] = row[tid];
    sRow[tid + 256] = row[tid + 256];
    __syncthreads();
    int c = tid & 31, g = tid >> 5;
    float a = 0.f;
    for (int k = g*64; k < (g+1)*64; k++) a = fmaf(sRow[k], Wp[(size_t)k*ADIM + c], a);
    part[g][c] = a;
    __syncthreads();
    if (tid < ADIM) {
        float s = bp[tid];
        #pragma unroll
        for (int g2 = 0; g2 < 8; g2++) s += part[g2][tid];
        out[(size_t)bt*ADIM + tid] = s;
    }
}

// ---------------- driver ----------------
extern "C" void kernel_launch(void* const* d_in, const int* in_sizes, int n_in,
                              void* d_out, int out_size)
{
    const int*   timesteps = (const int*)  d_in[0];
    const float* state_0   = (const float*)d_in[1];
    const float* state_1   = (const float*)d_in[2];
    const float* actions   = (const float*)d_in[3];
    const float* time_emb  = (const float*)d_in[4];
    const float* Ws  = (const float*)d_in[5];
    const float* bs  = (const float*)d_in[6];
    const float* Wa  = (const float*)d_in[7];
    const float* ba  = (const float*)d_in[8];
    const float* Wq  = (const float*)d_in[9];
    const float* bq  = (const float*)d_in[10];
    const float* Wk  = (const float*)d_in[11];
    const float* bk  = (const float*)d_in[12];
    const float* Wv  = (const float*)d_in[13];
    const float* bv  = (const float*)d_in[14];
    const float* Wo  = (const float*)d_in[15];
    const float* bo  = (const float*)d_in[16];
    const float* W1  = (const float*)d_in[17];
    const float* b1  = (const float*)d_in[18];
    const float* W2  = (const float*)d_in[19];
    const float* b2  = (const float*)d_in[20];
    const float* ln1_g = (const float*)d_in[21];
    const float* ln1_b = (const float*)d_in[22];
    const float* ln2_g = (const float*)d_in[23];
    const float* ln2_b = (const float*)d_in[24];
    const float* eln_g = (const float*)d_in[25];
    const float* eln_b = (const float*)d_in[26];
    const float* Wp  = (const float*)d_in[27];
    const float* bp  = (const float*)d_in[28];

    float *h, *v, *p0, *p1, *p2, *p3, *ln1o;
    uint2 *hs, *qs, *ks, *ctxs, *ln1s, *mlps, *ws;
    cudaGetSymbolAddress((void**)&h,    g_h);
    cudaGetSymbolAddress((void**)&v,    g_v);
    cudaGetSymbolAddress((void**)&p0,   g_p0);
    cudaGetSymbolAddress((void**)&p1,   g_p1);
    cudaGetSymbolAddress((void**)&p2,   g_p2);
    cudaGetSymbolAddress((void**)&p3,   g_p3);
    cudaGetSymbolAddress((void**)&ln1o, g_ln1);
    cudaGetSymbolAddress((void**)&hs,   g_hs);
    cudaGetSymbolAddress((void**)&qs,   g_qs);
    cudaGetSymbolAddress((void**)&ks,   g_ks);
    cudaGetSymbolAddress((void**)&ctxs, g_ctxs);
    cudaGetSymbolAddress((void**)&ln1s, g_ln1s);
    cudaGetSymbolAddress((void**)&mlps, g_mlps);
    cudaGetSymbolAddress((void**)&ws,   g_ws);

    cudaFuncSetAttribute(flash_kernel,
                         cudaFuncAttributeMaxDynamicSharedMemorySize, FLASH_SMEM);
    cudaFuncSetAttribute(tgemm_kernel,
                         cudaFuncAttributeMaxDynamicSharedMemorySize, SMG);
    cudaFuncSetAttribute(tgemm_sk_kernel,
                         cudaFuncAttributeMaxDynamicSharedMemorySize, SMG);
    cudaFuncSetAttribute(qkv_kernel,
                         cudaFuncAttributeMaxDynamicSharedMemorySize, SMG);

    // weights: transpose + split -> [blk][N][K/2]
    wtsplit_kernel<<<dim3(16, 4, 6),  256>>>(Wq, ws + WQ0, 512, 512);
    wtsplit_kernel<<<dim3(16, 4, 6),  256>>>(Wk, ws + WK0, 512, 512);
    wtsplit_kernel<<<dim3(16, 4, 6),  256>>>(Wv, ws + WV0, 512, 512);
    wtsplit_kernel<<<dim3(16, 4, 6),  256>>>(Wo, ws + WO0, 512, 512);
    wtsplit_kernel<<<dim3(16, 16, 6), 256>>>(W1, ws + W10, 512, 2048);
    wtsplit_kernel<<<dim3(64, 4, 6),  256>>>(W2, ws + W20, 2048, 512);

    embed_kernel<<<BB*SS, 256>>>(timesteps, state_0, state_1, actions, time_emb,
                                 Ws, bs, Wa, ba, eln_g, eln_b, h, hs);

    dim3 gQKV(HDIM/128, MROWS/128, 3);   // (4, 48, 3)
    dim3 gSK (HDIM/128, MROWS/128, 4);   // (4, 48, 4)
    dim3 gF  (DFF /128, MROWS/128);      // (16, 48)
    dim3 gFl (SS/128, BB*NH);            // (12, 32)

    for (int blk = 0; blk < NBLK; blk++) {
        const uint2* wqs = ws + WQ0 + (size_t)blk*131072;
        const uint2* wks = ws + WK0 + (size_t)blk*131072;
        const uint2* wvs = ws + WV0 + (size_t)blk*131072;
        const uint2* wos = ws + WO0 + (size_t)blk*131072;
        const uint2* w1s = ws + W10 + (size_t)blk*524288;
        const uint2* w2s = ws + W20 + (size_t)blk*524288;
        const float* bq_ = bq + (size_t)blk*HDIM;
        const float* bk_ = bk + (size_t)blk*HDIM;
        const float* bv_ = bv + (size_t)blk*HDIM;
        const float* bo_ = bo + (size_t)blk*HDIM;
        const float* b1_ = b1 + (size_t)blk*DFF;
        const float* b2_ = b2 + (size_t)blk*HDIM;
        const float* g1_ = ln1_g + (size_t)blk*HDIM;
        const float* e1_ = ln1_b + (size_t)blk*HDIM;
        const float* g2_ = ln2_g + (size_t)blk*HDIM;
        const float* e2_ = ln2_b + (size_t)blk*HDIM;

        qkv_kernel<<<gQKV, 128, SMG>>>(hs, wqs, wks, wvs, bq_, bk_, bv_, qs, ks, v);

        flash_kernel<<<gFl, 256, FLASH_SMEM>>>(qs, ks, v, ctxs);

        tgemm_sk_kernel<<<gSK, 128, SMG>>>(ctxs, wos, p0, p1, p2, p3, HDIM, HDIM);
        ln_sum_kernel<<<MROWS/8, 256>>>(p0, p1, p2, p3, bo_, h, g1_, e1_, ln1o, ln1s);
        tgemm_kernel<<<gF, 128, SMG>>>(ln1s, w1s, b1_, nullptr, mlps,
                                       DFF, HDIM, EP_GELU_SPLIT);
        tgemm_sk_kernel<<<gSK, 128, SMG>>>(mlps, w2s, p0, p1, p2, p3, HDIM, DFF);
        ln_sum_kernel<<<MROWS/8, 256>>>(p0, p1, p2, p3, b2_, ln1o, g2_, e2_, h, hs);
    }

    final_kernel<<<BB*TT, 256>>>(h, Wp, bp, (float*)d_out);
}

// round 14
// speedup vs baseline: 1.0173x; 1.0173x over previous
#include <cuda_runtime.h>
#include <cuda_bf16.h>
#include <math.h>

#define BB 4
#define TT 512
#define SS 1536
#define SDIM 64
#define ADIM 32
#define HDIM 512
#define HPH 256
#define NH 8
#define DH 64
#define NBLK 6
#define DFFH 1024
#define DFF 2048
#define MROWS (BB*SS)

enum { EP_BIAS = 0, EP_BIAS_RES = 1, EP_GELU_SPLIT = 2, EP_BIAS_SPLIT = 3 };

// ---------------- scratch ----------------
__device__ float g_h  [MROWS * HDIM];
__device__ float g_v  [MROWS * HDIM];
__device__ float g_p0 [MROWS * HDIM];
__device__ float g_p1 [MROWS * HDIM];
__device__ float g_ln1[MROWS * HDIM];

__device__ uint2 g_hs  [MROWS * HPH];
__device__ uint2 g_qs  [MROWS * HPH];
__device__ uint2 g_ks  [MROWS * HPH];
__device__ uint2 g_ctxs[MROWS * HPH];
__device__ uint2 g_ln1s[MROWS * HPH];
__device__ uint2 g_mlps[MROWS * DFFH];

#define WQ0 0
#define WK0 786432
#define WV0 1572864
#define WO0 2359296
#define W10 3145728
#define W20 6291456
__device__ uint2 g_ws[9437184];

// ---------------- bf16 split helpers ----------------
__device__ __forceinline__ uint2 split2bf(float x0, float x1) {
    __nv_bfloat162 h = __floats2bfloat162_rn(x0, x1);
    float r0 = x0 - __bfloat162float(h.x);
    float r1 = x1 - __bfloat162float(h.y);
    __nv_bfloat162 l = __floats2bfloat162_rn(r0, r1);
    uint2 out;
    out.x = *reinterpret_cast<unsigned*>(&h);
    out.y = *reinterpret_cast<unsigned*>(&l);
    return out;
}

__device__ __forceinline__ void mma16(float c[4],
    unsigned a0, unsigned a1, unsigned a2, unsigned a3,
    unsigned b0, unsigned b1)
{
    asm volatile(
      "mma.sync.aligned.m16n8k16.row.col.f32.bf16.bf16.f32 "
      "{%0,%1,%2,%3},{%4,%5,%6,%7},{%8,%9},{%0,%1,%2,%3};"
      : "+f"(c[0]), "+f"(c[1]), "+f"(c[2]), "+f"(c[3])
      : "r"(a0), "r"(a1), "r"(a2), "r"(a3), "r"(b0), "r"(b1));
}

__device__ __forceinline__ void cpa16(void* s, const void* g) {
    unsigned a = (unsigned)__cvta_generic_to_shared(s);
    asm volatile("cp.async.cg.shared.global [%0], [%1], 16;" :: "r"(a), "l"(g));
}
#define CP_COMMIT() asm volatile("cp.async.commit_group;")
#define CP_WAIT0()  asm volatile("cp.async.wait_group 0;")
#define CP_WAIT1()  asm volatile("cp.async.wait_group 1;")

// ---------------- reductions ----------------
__device__ __forceinline__ float blockReduceSum(float v, float* sm) {
    int lane = threadIdx.x & 31, wid = threadIdx.x >> 5;
    #pragma unroll
    for (int o = 16; o; o >>= 1) v += __shfl_down_sync(0xffffffffu, v, o);
    if (lane == 0) sm[wid] = v;
    __syncthreads();
    float r = 0.f;
    if (wid == 0) {
        r = (lane < 8) ? sm[lane] : 0.f;
        #pragma unroll
        for (int o = 4; o; o >>= 1) r += __shfl_down_sync(0xffffffffu, r, o);
        if (lane == 0) sm[0] = r;
    }
    __syncthreads();
    r = sm[0];
    __syncthreads();
    return r;
}

// ---------------- weight split: W[k][n] -> Ws[k/2][n] (hi,lo uint2) ----------
__global__ __launch_bounds__(256) void wsplit_kernel(
    const float* __restrict__ src, uint2* __restrict__ dst, int N)
{
    int n  = blockIdx.x * 256 + threadIdx.x;
    int kp = blockIdx.y;
    dst[(size_t)kp * N + n] =
        split2bf(src[(size_t)(2*kp) * N + n], src[(size_t)(2*kp + 1) * N + n]);
}

// ---------------- embedding + eLN ----------------
__global__ __launch_bounds__(256) void embed_kernel(
    const int* __restrict__ timesteps, const float* __restrict__ s0,
    const float* __restrict__ s1, const float* __restrict__ act,
    const float* __restrict__ temb,
    const float* __restrict__ Ws, const float* __restrict__ bs,
    const float* __restrict__ Wa, const float* __restrict__ ba,
    const float* __restrict__ eg, const float* __restrict__ eb,
    float* __restrict__ out, uint2* __restrict__ outs)
{
    int s = blockIdx.x;
    int b = s / SS, sr = s % SS;
    int t = sr / 3, r = sr % 3;

    __shared__ float sIn[SDIM];
    __shared__ float red[32];

    const float* inp; const float* W; const float* bias; int Kin;
    if (r == 0)      { inp = s0  + (size_t)(b*TT + t)*SDIM; W = Ws; bias = bs; Kin = SDIM; }
    else if (r == 1) { inp = s1  + (size_t)(b*TT + t)*SDIM; W = Ws; bias = bs; Kin = SDIM; }
    else             { inp = act + (size_t)(b*TT + t)*ADIM; W = Wa; bias = ba; Kin = ADIM; }

    int tid = threadIdx.x;
    if (tid < Kin) sIn[tid] = inp[tid];
    __syncthreads();

    int tsv = timesteps[b*TT + t];
    const float* te = temb + (size_t)tsv * HDIM;

    int c0 = 2*tid;
    float a0 = bias[c0] + te[c0], a1 = bias[c0+1] + te[c0+1];
    for (int k = 0; k < Kin; k++) {
        float x = sIn[k];
        a0 = fmaf(x, W[(size_t)k*HDIM + c0],     a0);
        a1 = fmaf(x, W[(size_t)k*HDIM + c0 + 1], a1);
    }
    float sum = blockReduceSum(a0 + a1, red);
    float m = sum * (1.0f / HDIM);
    float d0 = a0 - m, d1 = a1 - m;
    float ssq = blockReduceSum(d0*d0 + d1*d1, red);
    float rstd = rsqrtf(ssq * (1.0f / HDIM) + 1e-5f);
    float o0 = d0 * rstd * eg[c0]     + eb[c0];
    float o1 = d1 * rstd * eg[c0 + 1] + eb[c0 + 1];
    *(float2*)(out + (size_t)s*HDIM + c0) = make_float2(o0, o1);
    outs[(size_t)s*HPH + tid] = split2bf(o0, o1);
}

// ============ tensor-core GEMM (bf16x3, split operands) ========================
#define APAD 20
#define ASTG (128*APAD)

// full-K body (2-stage), 256 thr, tile 128xBN, warp grid 2x4
template<int BN>
__device__ __forceinline__ void tgemm_body(
    const uint2* __restrict__ A, const uint2* __restrict__ B,
    const float* __restrict__ bias,
    float* __restrict__ C, uint2* __restrict__ Cs,
    int M, int N, int K, int ep, float scl, char* smraw)
{
    constexpr int TNF = BN / 32;
    constexpr int BST = BN + 4;
    constexpr int BSTG = 16 * BST;
    uint2* Asm = (uint2*)smraw;
    uint2* Bsm = Asm + 2*ASTG;

    const int tid  = threadIdx.x, lane = tid & 31, warp = tid >> 5;
    const int g    = lane >> 2,  tg   = lane & 3;
    const int wm0  = (warp >> 2) * 64, wn0 = (warp & 3) * (BN / 4);
    const int m0   = blockIdx.y * 128, n0 = blockIdx.x * BN;
    const int KW   = K >> 1;

    float acc[4][TNF][4];
    #pragma unroll
    for (int i = 0; i < 4; i++)
        #pragma unroll
        for (int j = 0; j < TNF; j++)
            #pragma unroll
            for (int l = 0; l < 4; l++) acc[i][j][l] = 0.f;

    const int T = K / 32;

    auto fill = [&](int t, int s) {
        uint2* Ad = Asm + s*ASTG;
        uint2* Bd = Bsm + s*BSTG;
        int kw0 = t * 16;
        #pragma unroll
        for (int i = 0; i < 4; i++) {
            int id = tid + 256*i, r = id >> 3, c = (id & 7) * 2;
            cpa16(Ad + r*APAD + c, A + (size_t)(m0 + r)*KW + kw0 + c);
        }
        if (BN == 128) {
            #pragma unroll
            for (int i = 0; i < 4; i++) {
                int id = tid + 256*i, kp = id >> 6, nc = (id & 63) * 2;
                cpa16(Bd + kp*BST + nc, B + (size_t)(kw0 + kp)*N + n0 + nc);
            }
        } else {
            #pragma unroll
            for (int i = 0; i < 2; i++) {
                int id = tid + 256*i, kp = id >> 5, nc = (id & 31) * 2;
                cpa16(Bd + kp*BST + nc, B + (size_t)(kw0 + kp)*N + n0 + nc);
            }
        }
        CP_COMMIT();
    };

    fill(0, 0);

    for (int t = 0; t < T; t++) {
        const int s = t & 1;
        CP_WAIT0();
        __syncthreads();
        if (t + 1 < T) fill(t + 1, s ^ 1);

        const uint2* As_ = Asm + s*ASTG;
        const uint2* Bs_ = Bsm + s*BSTG;
        #pragma unroll
        for (int ks = 0; ks < 2; ks++) {
            const int kb = ks * 8;
            uint2 bf[TNF][2];
            #pragma unroll
            for (int tn = 0; tn < TNF; tn++) {
                int n = wn0 + tn*8 + g;
                bf[tn][0] = Bs_[(kb + tg)*BST + n];
                bf[tn][1] = Bs_[(kb + tg + 4)*BST + n];
            }
            #pragma unroll
            for (int tm = 0; tm < 4; tm++) {
                int m = wm0 + tm*16 + g;
                uint2 a0 = As_[m*APAD + kb + tg];
                uint2 a1 = As_[(m+8)*APAD + kb + tg];
                uint2 a2 = As_[m*APAD + kb + tg + 4];
                uint2 a3 = As_[(m+8)*APAD + kb + tg + 4];
                #pragma unroll
                for (int tn = 0; tn < TNF; tn++) {
                    mma16(acc[tm][tn], a0.x,a1.x,a2.x,a3.x, bf[tn][0].x, bf[tn][1].x);
                    mma16(acc[tm][tn], a0.y,a1.y,a2.y,a3.y, bf[tn][0].x, bf[tn][1].x);
                    mma16(acc[tm][tn], a0.x,a1.x,a2.x,a3.x, bf[tn][0].y, bf[tn][1].y);
                }
            }
        }
    }

    #pragma unroll
    for (int tm = 0; tm < 4; tm++) {
        #pragma unroll
        for (int tn = 0; tn < TNF; tn++) {
            int row = m0 + wm0 + tm*16 + g;
            int col = n0 + wn0 + tn*8 + tg*2;
            float b0v = bias[col], b1v = bias[col+1];
            float v00 = acc[tm][tn][0] + b0v, v01 = acc[tm][tn][1] + b1v;
            float v10 = acc[tm][tn][2] + b0v, v11 = acc[tm][tn][3] + b1v;
            if (ep == EP_BIAS) {
                *(float2*)(C + (size_t)row*N + col)     = make_float2(v00, v01);
                *(float2*)(C + (size_t)(row+8)*N + col) = make_float2(v10, v11);
            } else {
                if (ep == EP_GELU_SPLIT) {
                    v00 = 0.5f*v00*(1.0f + erff(v00*0.70710678118654752f));
                    v01 = 0.5f*v01*(1.0f + erff(v01*0.70710678118654752f));
                    v10 = 0.5f*v10*(1.0f + erff(v10*0.70710678118654752f));
                    v11 = 0.5f*v11*(1.0f + erff(v11*0.70710678118654752f));
                } else {
                    v00 *= scl; v01 *= scl; v10 *= scl; v11 *= scl;
                }
                Cs[(size_t)row*(N>>1)     + (col>>1)] = split2bf(v00, v01);
                Cs[(size_t)(row+8)*(N>>1) + (col>>1)] = split2bf(v10, v11);
            }
        }
    }
}

template<int BN>
__global__ __launch_bounds__(256, 2) void tgemm_kernel(
    const uint2* __restrict__ A, const uint2* __restrict__ B,
    const float* __restrict__ bias,
    float* __restrict__ C, uint2* __restrict__ Cs,
    int M, int N, int K, int ep)
{
    extern __shared__ char smraw[];
    tgemm_body<BN>(A, B, bias, C, Cs, M, N, K, ep, 1.0f, smraw);
}

// ---------- split-K (2-way) GEMM, BN=64, 3-stage pipeline ---------------------
__global__ __launch_bounds__(256, 2) void tgemm_splitk_kernel(
    const uint2* __restrict__ A, const uint2* __restrict__ B,
    float* __restrict__ P0, float* __restrict__ P1,
    int N, int K)
{
    constexpr int BN = 64, TNF = 2, BST = BN + 4, BSTG = 16 * BST;
    extern __shared__ char smraw[];
    uint2* Asm = (uint2*)smraw;
    uint2* Bsm = Asm + 3*ASTG;

    const int tid  = threadIdx.x, lane = tid & 31, warp = tid >> 5;
    const int g    = lane >> 2,  tg   = lane & 3;
    const int wm0  = (warp >> 2) * 64, wn0 = (warp & 3) * 16;
    const int m0   = blockIdx.y * 128, n0 = blockIdx.x * BN;
    const int z    = blockIdx.z;
    const int KW   = K >> 1;
    const int KWS  = KW >> 1;
    const int kwb  = z * KWS;
    float* P = z ? P1 : P0;

    float acc[4][TNF][4];
    #pragma unroll
    for (int i = 0; i < 4; i++)
        #pragma unroll
        for (int j = 0; j < TNF; j++)
            #pragma unroll
            for (int l = 0; l < 4; l++) acc[i][j][l] = 0.f;

    const int T = (K / 2) / 32;

    auto fill = [&](int t, int s) {
        uint2* Ad = Asm + s*ASTG;
        uint2* Bd = Bsm + s*BSTG;
        int kw0 = kwb + t * 16;
        #pragma unroll
        for (int i = 0; i < 4; i++) {
            int id = tid + 256*i, r = id >> 3, c = (id & 7) * 2;
            cpa16(Ad + r*APAD + c, A + (size_t)(m0 + r)*KW + kw0 + c);
        }
        #pragma unroll
        for (int i = 0; i < 2; i++) {
            int id = tid + 256*i, kp = id >> 5, nc = (id & 31) * 2;
            cpa16(Bd + kp*BST + nc, B + (size_t)(kw0 + kp)*N + n0 + nc);
        }
        CP_COMMIT();
    };

    fill(0, 0);
    if (T > 1) fill(1, 1);

    for (int t = 0; t < T; t++) {
        const int s = t % 3;
        if (t + 1 < T) CP_WAIT1(); else CP_WAIT0();
        __syncthreads();
        if (t + 2 < T) fill(t + 2, (t + 2) % 3);

        const uint2* As_ = Asm + s*ASTG;
        const uint2* Bs_ = Bsm + s*BSTG;
        #pragma unroll
        for (int ks = 0; ks < 2; ks++) {
            const int kb = ks * 8;
            uint2 bf[TNF][2];
            #pragma unroll
            for (int tn = 0; tn < TNF; tn++) {
                int n = wn0 + tn*8 + g;
                bf[tn][0] = Bs_[(kb + tg)*BST + n];
                bf[tn][1] = Bs_[(kb + tg + 4)*BST + n];
            }
            #pragma unroll
            for (int tm = 0; tm < 4; tm++) {
                int m = wm0 + tm*16 + g;
                uint2 a0 = As_[m*APAD + kb + tg];
                uint2 a1 = As_[(m+8)*APAD + kb + tg];
                uint2 a2 = As_[m*APAD + kb + tg + 4];
                uint2 a3 = As_[(m+8)*APAD + kb + tg + 4];
                #pragma unroll
                for (int tn = 0; tn < TNF; tn++) {
                    mma16(acc[tm][tn], a0.x,a1.x,a2.x,a3.x, bf[tn][0].x, bf[tn][1].x);
                    mma16(acc[tm][tn], a0.y,a1.y,a2.y,a3.y, bf[tn][0].x, bf[tn][1].x);
                    mma16(acc[tm][tn], a0.x,a1.x,a2.x,a3.x, bf[tn][0].y, bf[tn][1].y);
                }
            }
        }
    }

    #pragma unroll
    for (int tm = 0; tm < 4; tm++)
        #pragma unroll
        for (int tn = 0; tn < TNF; tn++) {
            int row = m0 + wm0 + tm*16 + g;
            int col = n0 + wn0 + tn*8 + tg*2;
            *(float2*)(P + (size_t)row*N + col)     = make_float2(acc[tm][tn][0], acc[tm][tn][1]);
            *(float2*)(P + (size_t)(row+8)*N + col) = make_float2(acc[tm][tn][2], acc[tm][tn][3]);
        }
}

// fused QKV (q scaled by 1/8 pre-split; v fp32)
__global__ __launch_bounds__(256, 2) void qkv_kernel(
    const uint2* __restrict__ hs,
    const uint2* __restrict__ wq, const uint2* __restrict__ wk, const uint2* __restrict__ wv,
    const float* __restrict__ bq, const float* __restrict__ bk, const float* __restrict__ bv,
    uint2* __restrict__ qs, uint2* __restrict__ ks, float* __restrict__ v)
{
    extern __shared__ char smraw[];
    if (blockIdx.z == 0)
        tgemm_body<128>(hs, wq, bq, nullptr, qs, MROWS, HDIM, HDIM, EP_BIAS_SPLIT, 0.125f, smraw);
    else if (blockIdx.z == 1)
        tgemm_body<128>(hs, wk, bk, nullptr, ks, MROWS, HDIM, HDIM, EP_BIAS_SPLIT, 1.0f, smraw);
    else
        tgemm_body<128>(hs, wv, bv, v, nullptr, MROWS, HDIM, HDIM, EP_BIAS, 1.0f, smraw);
}

#define SM128  (2*(ASTG + 16*132)*(int)sizeof(uint2))
#define SM64_3 (3*(ASTG + 16*68 )*(int)sizeof(uint2))

// ================= flash attention =============================================
#define FLASH_KPAD 132
#define FLASH_VPAD 68
#define FLASH_SMEM ((32*FLASH_KPAD + 64*FLASH_VPAD) * (int)sizeof(uint2))

__global__ __launch_bounds__(256) void flash_kernel(
    const uint2* __restrict__ q, const uint2* __restrict__ k,
    const float* __restrict__ v, uint2* __restrict__ ctxs)
{
    extern __shared__ uint2 dsmem[];
    uint2 (*Ks)[FLASH_KPAD] = reinterpret_cast<uint2(*)[FLASH_KPAD]>(dsmem);
    uint2 (*Vs)[FLASH_VPAD] = reinterpret_cast<uint2(*)[FLASH_VPAD]>(dsmem + 32*FLASH_KPAD);

    const int it = (int)(gridDim.x - 1 - blockIdx.x);
    const int bh = blockIdx.y, b = bh >> 3, h = bh & 7;
    const uint2* qb = q + (size_t)b*SS*HPH + h*32;
    const uint2* kb = k + (size_t)b*SS*HPH + h*32;
    const float* vb = v + (size_t)b*SS*HDIM + h*DH;
    uint2* cb       = ctxs + (size_t)b*SS*HPH + h*32;

    const int tid  = threadIdx.x, lane = tid & 31, warp = tid >> 5;
    const int g    = lane >> 2,  tg   = lane & 3;
    const int i0   = it * 128;
    const int rowg = i0 + warp*16 + g;

    uint2 qf[4][4];
    {
        const uint2* qrg = qb + (size_t)rowg*HPH;
        const uint2* qr8 = qrg + 8*HPH;
        #pragma unroll
        for (int kk = 0; kk < 4; kk++) {
            qf[kk][0] = qrg[kk*8 + tg];
            qf[kk][1] = qr8[kk*8 + tg];
            qf[kk][2] = qrg[kk*8 + tg + 4];
            qf[kk][3] = qr8[kk*8 + tg + 4];
        }
    }

    float m0 = -1e30f, m1 = -1e30f, l0 = 0.f, l1 = 0.f;
    float o[8][4];
    #pragma unroll
    for (int nf = 0; nf < 8; nf++)
        #pragma unroll
        for (int l = 0; l < 4; l++) o[nf][l] = 0.f;

    const int kjr = tid >> 1, kcb = (tid & 1)*16;
    const int vjp = tid >> 2, vcb = (tid & 3)*16;

    for (int jt = 0; jt <= it; jt++) {
        const int j0 = jt * 128;
        {
            const uint2* krow = kb + (size_t)(j0 + kjr)*HPH + kcb;
            #pragma unroll
            for (int u = 0; u < 8; u++) {
                uint4 f = ((const uint4*)krow)[u];
                Ks[kcb + 2*u][kjr]     = make_uint2(f.x, f.y);
                Ks[kcb + 2*u + 1][kjr] = make_uint2(f.z, f.w);
            }
        }
        {
            const float* vr0 = vb + (size_t)(j0 + 2*vjp)*HDIM + vcb;
            const float* vr1 = vr0 + HDIM;
            #pragma unroll
            for (int u = 0; u < 4; u++) {
                float4 f0 = *(const float4*)(vr0 + u*4);
                float4 f1 = *(const float4*)(vr1 + u*4);
                Vs[vjp][vcb + u*4 + 0] = split2bf(f0.x, f1.x);
                Vs[vjp][vcb + u*4 + 1] = split2bf(f0.y, f1.y);
                Vs[vjp][vcb + u*4 + 2] = split2bf(f0.z, f1.z);
                Vs[vjp][vcb + u*4 + 3] = split2bf(f0.w, f1.w);
            }
        }
        __syncthreads();

        float s[16][4];
        #pragma unroll
        for (int jf = 0; jf < 16; jf++)
            #pragma unroll
            for (int l = 0; l < 4; l++) s[jf][l] = 0.f;

        #pragma unroll
        for (int kk = 0; kk < 4; kk++) {
            uint2 a0 = qf[kk][0], a1 = qf[kk][1], a2 = qf[kk][2], a3 = qf[kk][3];
            #pragma unroll
            for (int jf = 0; jf < 16; jf++) {
                uint2 b0 = Ks[kk*8 + tg][jf*8 + g];
                uint2 b1 = Ks[kk*8 + tg + 4][jf*8 + g];
                mma16(s[jf], a0.x,a1.x,a2.x,a3.x, b0.x, b1.x);
                mma16(s[jf], a0.y,a1.y,a2.y,a3.y, b0.x, b1.x);
                mma16(s[jf], a0.x,a1.x,a2.x,a3.x, b0.y, b1.y);
            }
        }

        if (jt == it) {
            const int r0 = warp*16 + g, r1 = r0 + 8;
            #pragma unroll
            for (int jf = 0; jf < 16; jf++) {
                int c0 = jf*8 + 2*tg;
                if (c0     > r0) s[jf][0] = -1e30f;
                if (c0 + 1 > r0) s[jf][1] = -1e30f;
                if (c0     > r1) s[jf][2] = -1e30f;
                if (c0 + 1 > r1) s[jf][3] = -1e30f;
            }
        }

        float tm0 = -1e30f, tm1 = -1e30f;
        #pragma unroll
        for (int jf = 0; jf < 16; jf++) {
            tm0 = fmaxf(tm0, fmaxf(s[jf][0], s[jf][1]));
            tm1 = fmaxf(tm1, fmaxf(s[jf][2], s[jf][3]));
        }
        tm0 = fmaxf(tm0, __shfl_xor_sync(0xffffffffu, tm0, 1));
        tm0 = fmaxf(tm0, __shfl_xor_sync(0xffffffffu, tm0, 2));
        tm1 = fmaxf(tm1, __shfl_xor_sync(0xffffffffu, tm1, 1));
        tm1 = fmaxf(tm1, __shfl_xor_sync(0xffffffffu, tm1, 2));

        float nm0 = fmaxf(m0, tm0), nm1 = fmaxf(m1, tm1);
        float al0 = __expf(m0 - nm0), al1 = __expf(m1 - nm1);
        m0 = nm0; m1 = nm1;

        float rs0 = 0.f, rs1 = 0.f;
        #pragma unroll
        for (int jf = 0; jf < 16; jf++) {
            s[jf][0] = __expf(s[jf][0] - nm0);
            s[jf][1] = __expf(s[jf][1] - nm0);
            s[jf][2] = __expf(s[jf][2] - nm1);
            s[jf][3] = __expf(s[jf][3] - nm1);
            rs0 += s[jf][0] + s[jf][1];
            rs1 += s[jf][2] + s[jf][3];
        }
        rs0 += __shfl_xor_sync(0xffffffffu, rs0, 1);
        rs0 += __shfl_xor_sync(0xffffffffu, rs0, 2);
        rs1 += __shfl_xor_sync(0xffffffffu, rs1, 1);
        rs1 += __shfl_xor_sync(0xffffffffu, rs1, 2);
        l0 = l0*al0 + rs0;
        l1 = l1*al1 + rs1;

        #pragma unroll
        for (int nf = 0; nf < 8; nf++) {
            o[nf][0] *= al0; o[nf][1] *= al0;
            o[nf][2] *= al1; o[nf][3] *= al1;
        }

        #pragma unroll
        for (int kk = 0; kk < 8; kk++) {
            uint2 A0 = split2bf(s[2*kk][0],   s[2*kk][1]);
            uint2 A1 = split2bf(s[2*kk][2],   s[2*kk][3]);
            uint2 A2 = split2bf(s[2*kk+1][0], s[2*kk+1][1]);
            uint2 A3 = split2bf(s[2*kk+1][2], s[2*kk+1][3]);
            #pragma unroll
            for (int nf = 0; nf < 8; nf++) {
                uint2 b0 = Vs[kk*8 + tg][nf*8 + g];
                uint2 b1 = Vs[kk*8 + tg + 4][nf*8 + g];
                mma16(o[nf], A0.x,A1.x,A2.x,A3.x, b0.x, b1.x);
                mma16(o[nf], A0.y,A1.y,A2.y,A3.y, b0.x, b1.x);
                mma16(o[nf], A0.x,A1.x,A2.x,A3.x, b0.y, b1.y);
            }
        }
        __syncthreads();
    }

    float inv0 = 1.0f / l0, inv1 = 1.0f / l1;
    uint2* crow0 = cb + (size_t)rowg*HPH;
    uint2* crow1 = crow0 + 8*HPH;
    #pragma unroll
    for (int nf = 0; nf < 8; nf++) {
        crow0[nf*4 + tg] = split2bf(o[nf][0]*inv0, o[nf][1]*inv0);
        crow1[nf*4 + tg] = split2bf(o[nf][2]*inv1, o[nf][3]*inv1);
    }
}

// ---------- layernorm over (p0 + p1 + bias + res): warp-per-row ---------------
__global__ __launch_bounds__(256) void ln_sum_kernel(
    const float* __restrict__ p0, const float* __restrict__ p1,
    const float* __restrict__ bias, const float* __restrict__ res,
    const float* __restrict__ g, const float* __restrict__ b,
    float* __restrict__ out, uint2* __restrict__ outs)
{
    int row  = blockIdx.x * 8 + (threadIdx.x >> 5);
    int lane = threadIdx.x & 31;
    const float* p0r = p0 + (size_t)row * HDIM;
    const float* p1r = p1 + (size_t)row * HDIM;
    const float* rr  = res + (size_t)row * HDIM;

    float4 xv[4];
    float sum = 0.f;
    #pragma unroll
    for (int i = 0; i < 4; i++) {
        int c = lane*4 + i*128;
        float4 a = *(const float4*)(p0r + c);
        float4 d = *(const float4*)(p1r + c);
        float4 e = *(const float4*)(bias + c);
        float4 f = *(const float4*)(rr + c);
        xv[i].x = a.x + d.x + e.x + f.x;
        xv[i].y = a.y + d.y + e.y + f.y;
        xv[i].z = a.z + d.z + e.z + f.z;
        xv[i].w = a.w + d.w + e.w + f.w;
        sum += (xv[i].x + xv[i].y) + (xv[i].z + xv[i].w);
    }
    #pragma unroll
    for (int o = 16; o; o >>= 1) sum += __shfl_xor_sync(0xffffffffu, sum, o);
    float m = sum * (1.0f / HDIM);

    float ssq = 0.f;
    #pragma unroll
    for (int i = 0; i < 4; i++) {
        xv[i].x -= m; xv[i].y -= m; xv[i].z -= m; xv[i].w -= m;
        ssq += xv[i].x*xv[i].x + xv[i].y*xv[i].y + xv[i].z*xv[i].z + xv[i].w*xv[i].w;
    }
    #pragma unroll
    for (int o = 16; o; o >>= 1) ssq += __shfl_xor_sync(0xffffffffu, ssq, o);
    float rstd = rsqrtf(ssq * (1.0f / HDIM) + 1e-5f);

    float* outr = out + (size_t)row * HDIM;
    uint2* outsr = outs + (size_t)row * HPH;
    #pragma unroll
    for (int i = 0; i < 4; i++) {
        int c = lane*4 + i*128;
        float4 gv = *(const float4*)(g + c);
        float4 bv = *(const float4*)(b + c);
        float4 ov;
        ov.x = xv[i].x * rstd * gv.x + bv.x;
        ov.y = xv[i].y * rstd * gv.y + bv.y;
        ov.z = xv[i].z * rstd * gv.z + bv.z;
        ov.w = xv[i].w * rstd * gv.w + bv.w;
        *(float4*)(outr + c) = ov;
        outsr[(c >> 1)    ] = split2bf(ov.x, ov.y);
        outsr[(c >> 1) + 1] = split2bf(ov.z, ov.w);
    }
}

// ---------------- final projection ----------------
__global__ __launch_bounds__(256) void final_kernel(
    const float* __restrict__ h, const float* __restrict__ Wp,
    const float* __restrict__ bp, float* __restrict__ out)
{
    int bt = blockIdx.x;
    int b = bt / TT, t = bt % TT;
    const float* row = h + ((size_t)b*SS + 3*t + 1) * HDIM;
    __shared__ float sRow[HDIM];
    __shared__ float part[8][ADIM];
    int tid = threadIdx.x;
    sRow[tid] = row[tid];
    sRow[tid + 256] = row[tid + 256];
    __syncthreads();
    int c = tid & 31, g = tid >> 5;
    float a = 0.f;
    for (int k = g*64; k < (g+1)*64; k++) a = fmaf(sRow[k], Wp[(size_t)k*ADIM + c], a);
    part[g][c] = a;
    __syncthreads();
    if (tid < ADIM) {
        float s = bp[tid];
        #pragma unroll
        for (int g2 = 0; g2 < 8; g2++) s += part[g2][tid];
        out[(size_t)bt*ADIM + tid] = s;
    }
}

// ---------------- driver ----------------
extern "C" void kernel_launch(void* const* d_in, const int* in_sizes, int n_in,
                              void* d_out, int out_size)
{
    const int*   timesteps = (const int*)  d_in[0];
    const float* state_0   = (const float*)d_in[1];
    const float* state_1   = (const float*)d_in[2];
    const float* actions   = (const float*)d_in[3];
    const float* time_emb  = (const float*)d_in[4];
    const float* Ws  = (const float*)d_in[5];
    const float* bs  = (const float*)d_in[6];
    const float* Wa  = (const float*)d_in[7];
    const float* ba  = (const float*)d_in[8];
    const float* Wq  = (const float*)d_in[9];
    const float* bq  = (const float*)d_in[10];
    const float* Wk  = (const float*)d_in[11];
    const float* bk  = (const float*)d_in[12];
    const float* Wv  = (const float*)d_in[13];
    const float* bv  = (const float*)d_in[14];
    const float* Wo  = (const float*)d_in[15];
    const float* bo  = (const float*)d_in[16];
    const float* W1  = (const float*)d_in[17];
    const float* b1  = (const float*)d_in[18];
    const float* W2  = (const float*)d_in[19];
    const float* b2  = (const float*)d_in[20];
    const float* ln1_g = (const float*)d_in[21];
    const float* ln1_b = (const float*)d_in[22];
    const float* ln2_g = (const float*)d_in[23];
    const float* ln2_b = (const float*)d_in[24];
    const float* eln_g = (const float*)d_in[25];
    const float* eln_b = (const float*)d_in[26];
    const float* Wp  = (const float*)d_in[27];
    const float* bp  = (const float*)d_in[28];

    float *h, *v, *p0, *p1, *ln1o;
    uint2 *hs, *qs, *ks, *ctxs, *ln1s, *mlps, *ws;
    cudaGetSymbolAddress((void**)&h,    g_h);
    cudaGetSymbolAddress((void**)&v,    g_v);
    cudaGetSymbolAddress((void**)&p0,   g_p0);
    cudaGetSymbolAddress((void**)&p1,   g_p1);
    cudaGetSymbolAddress((void**)&ln1o, g_ln1);
    cudaGetSymbolAddress((void**)&hs,   g_hs);
    cudaGetSymbolAddress((void**)&qs,   g_qs);
    cudaGetSymbolAddress((void**)&ks,   g_ks);
    cudaGetSymbolAddress((void**)&ctxs, g_ctxs);
    cudaGetSymbolAddress((void**)&ln1s, g_ln1s);
    cudaGetSymbolAddress((void**)&mlps, g_mlps);
    cudaGetSymbolAddress((void**)&ws,   g_ws);

    cudaFuncSetAttribute(flash_kernel,
                         cudaFuncAttributeMaxDynamicSharedMemorySize, FLASH_SMEM);
    cudaFuncSetAttribute(tgemm_kernel<128>,
                         cudaFuncAttributeMaxDynamicSharedMemorySize, SM128);
    cudaFuncSetAttribute(tgemm_splitk_kernel,
                         cudaFuncAttributeMaxDynamicSharedMemorySize, SM64_3);
    cudaFuncSetAttribute(qkv_kernel,
                         cudaFuncAttributeMaxDynamicSharedMemorySize, SM128);

    wsplit_kernel<<<dim3(HDIM/256, NBLK*HDIM/2), 256>>>(Wq, ws + WQ0, HDIM);
    wsplit_kernel<<<dim3(HDIM/256, NBLK*HDIM/2), 256>>>(Wk, ws + WK0, HDIM);
    wsplit_kernel<<<dim3(HDIM/256, NBLK*HDIM/2), 256>>>(Wv, ws + WV0, HDIM);
    wsplit_kernel<<<dim3(HDIM/256, NBLK*HDIM/2), 256>>>(Wo, ws + WO0, HDIM);
    wsplit_kernel<<<dim3(DFF/256,  NBLK*HDIM/2), 256>>>(W1, ws + W10, DFF);
    wsplit_kernel<<<dim3(HDIM/256, NBLK*DFF/2),  256>>>(W2, ws + W20, HDIM);

    embed_kernel<<<BB*SS, 256>>>(timesteps, state_0, state_1, actions, time_emb,
                                 Ws, bs, Wa, ba, eln_g, eln_b, h, hs);

    dim3 gQKV(HDIM/128, MROWS/128, 3);   // (4, 48, 3)
    dim3 gSK (HDIM/64,  MROWS/128, 2);   // (8, 48, 2)
    dim3 gF  (DFF /128, MROWS/128);      // (16, 48)
    dim3 gFl (SS/128, BB*NH);            // (12, 32)

    for (int blk = 0; blk < NBLK; blk++) {
        const uint2* wqs = ws + WQ0 + (size_t)blk*131072;
        const uint2* wks = ws + WK0 + (size_t)blk*131072;
        const uint2* wvs = ws + WV0 + (size_t)blk*131072;
        const uint2* wos = ws + WO0 + (size_t)blk*131072;
        const uint2* w1s = ws + W10 + (size_t)blk*524288;
        const uint2* w2s = ws + W20 + (size_t)blk*524288;
        const float* bq_ = bq + (size_t)blk*HDIM;
        const float* bk_ = bk + (size_t)blk*HDIM;
        const float* bv_ = bv + (size_t)blk*HDIM;
        const float* bo_ = bo + (size_t)blk*HDIM;
        const float* b1_ = b1 + (size_t)blk*DFF;
        const float* b2_ = b2 + (size_t)blk*HDIM;
        const float* g1_ = ln1_g + (size_t)blk*HDIM;
        const float* e1_ = ln1_b + (size_t)blk*HDIM;
        const float* g2_ = ln2_g + (size_t)blk*HDIM;
        const float* e2_ = ln2_b + (size_t)blk*HDIM;

        qkv_kernel<<<gQKV, 256, SM128>>>(hs, wqs, wks, wvs, bq_, bk_, bv_, qs, ks, v);

        flash_kernel<<<gFl, 256, FLASH_SMEM>>>(qs, ks, v, ctxs);

        tgemm_splitk_kernel<<<gSK, 256, SM64_3>>>(ctxs, wos, p0, p1, HDIM, HDIM);
        ln_sum_kernel<<<MROWS/8, 256>>>(p0, p1, bo_, h, g1_, e1_, ln1o, ln1s);
        tgemm_kernel<128><<<gF, 256, SM128>>>(ln1s, w1s, b1_, nullptr, mlps,
                                              MROWS, DFF, HDIM, EP_GELU_SPLIT);
        tgemm_splitk_kernel<<<gSK, 256, SM64_3>>>(mlps, w2s, p0, p1, HDIM, DFF);
        ln_sum_kernel<<<MROWS/8, 256>>>(p0, p1, b2_, ln1o, g2_, e2_, h, hs);
    }

    final_kernel<<<BB*TT, 256>>>(h, Wp, bp, (float*)d_out);
}

// round 15
// speedup vs baseline: 1.5788x; 1.5519x over previous
#include <cuda_runtime.h>
#include <cuda_fp16.h>
#include <math.h>

#define BB 4
#define TT 512
#define SS 1536
#define SDIM 64
#define ADIM 32
#define HDIM 512
#define HPH 256
#define NH 8
#define DH 64
#define NBLK 6
#define DFFH 1024
#define DFF 2048
#define MROWS (BB*SS)

enum { EP_BIAS = 0, EP_GELU_SPLIT = 2, EP_BIAS_SPLIT = 3, EP_BIAS_PACK = 4 };

// ---------------- scratch ----------------
__device__ float g_h  [MROWS * HDIM];
__device__ float g_v  [MROWS * HDIM];
__device__ float g_p0 [MROWS * HDIM];
__device__ float g_p1 [MROWS * HDIM];
__device__ float g_ln1[MROWS * HDIM];

__device__ uint2 g_hs  [MROWS * HPH];      // split fp16 (hi,lo) pairs
__device__ uint2 g_qs  [MROWS * HPH];
__device__ unsigned g_ksp[MROWS * HPH];    // K: single fp16 pairs
__device__ uint2 g_ctxs[MROWS * HPH];
__device__ uint2 g_ln1s[MROWS * HPH];
__device__ uint2 g_mlps[MROWS * DFFH];

// weight planes: single fp16 pairs [blk][k/2][n]
#define WQ0 0
#define WK0 786432
#define WV0 1572864
#define WO0 2359296
#define W10 3145728
#define W20 6291456
__device__ unsigned g_ws[9437184];

// ---------------- fp16 helpers ----------------
__device__ __forceinline__ uint2 split2h(float x0, float x1) {
    __half h0 = __float2half_rn(x0), h1 = __float2half_rn(x1);
    __half l0 = __float2half_rn(x0 - __half2float(h0));
    __half l1 = __float2half_rn(x1 - __half2float(h1));
    __half2 hh = __halves2half2(h0, h1);
    __half2 ll = __halves2half2(l0, l1);
    uint2 o;
    o.x = *reinterpret_cast<unsigned*>(&hh);
    o.y = *reinterpret_cast<unsigned*>(&ll);
    return o;
}
__device__ __forceinline__ unsigned pack2h(float x0, float x1) {
    __half2 hh = __floats2half2_rn(x0, x1);
    return *reinterpret_cast<unsigned*>(&hh);
}

__device__ __forceinline__ void mma16(float c[4],
    unsigned a0, unsigned a1, unsigned a2, unsigned a3,
    unsigned b0, unsigned b1)
{
    asm volatile(
      "mma.sync.aligned.m16n8k16.row.col.f32.f16.f16.f32 "
      "{%0,%1,%2,%3},{%4,%5,%6,%7},{%8,%9},{%0,%1,%2,%3};"
      : "+f"(c[0]), "+f"(c[1]), "+f"(c[2]), "+f"(c[3])
      : "r"(a0), "r"(a1), "r"(a2), "r"(a3), "r"(b0), "r"(b1));
}

__device__ __forceinline__ void cpa16(void* s, const void* g) {
    unsigned a = (unsigned)__cvta_generic_to_shared(s);
    asm volatile("cp.async.cg.shared.global [%0], [%1], 16;" :: "r"(a), "l"(g));
}
#define CP_COMMIT() asm volatile("cp.async.commit_group;")
#define CP_WAIT0()  asm volatile("cp.async.wait_group 0;")
#define CP_WAIT1()  asm volatile("cp.async.wait_group 1;")

// ---------------- reductions ----------------
__device__ __forceinline__ float blockReduceSum(float v, float* sm) {
    int lane = threadIdx.x & 31, wid = threadIdx.x >> 5;
    #pragma unroll
    for (int o = 16; o; o >>= 1) v += __shfl_down_sync(0xffffffffu, v, o);
    if (lane == 0) sm[wid] = v;
    __syncthreads();
    float r = 0.f;
    if (wid == 0) {
        r = (lane < 8) ? sm[lane] : 0.f;
        #pragma unroll
        for (int o = 4; o; o >>= 1) r += __shfl_down_sync(0xffffffffu, r, o);
        if (lane == 0) sm[0] = r;
    }
    __syncthreads();
    r = sm[0];
    __syncthreads();
    return r;
}

// ---------------- weight pack: W[k][n] -> Wp[k/2][n] fp16 pairs --------------
__global__ __launch_bounds__(256) void wsplit_kernel(
    const float* __restrict__ src, unsigned* __restrict__ dst, int N)
{
    int n  = blockIdx.x * 256 + threadIdx.x;
    int kp = blockIdx.y;
    dst[(size_t)kp * N + n] =
        pack2h(src[(size_t)(2*kp) * N + n], src[(size_t)(2*kp + 1) * N + n]);
}

// ---------------- embedding + eLN ----------------
__global__ __launch_bounds__(256) void embed_kernel(
    const int* __restrict__ timesteps, const float* __restrict__ s0,
    const float* __restrict__ s1, const float* __restrict__ act,
    const float* __restrict__ temb,
    const float* __restrict__ Ws, const float* __restrict__ bs,
    const float* __restrict__ Wa, const float* __restrict__ ba,
    const float* __restrict__ eg, const float* __restrict__ eb,
    float* __restrict__ out, uint2* __restrict__ outs)
{
    int s = blockIdx.x;
    int b = s / SS, sr = s % SS;
    int t = sr / 3, r = sr % 3;

    __shared__ float sIn[SDIM];
    __shared__ float red[32];

    const float* inp; const float* W; const float* bias; int Kin;
    if (r == 0)      { inp = s0  + (size_t)(b*TT + t)*SDIM; W = Ws; bias = bs; Kin = SDIM; }
    else if (r == 1) { inp = s1  + (size_t)(b*TT + t)*SDIM; W = Ws; bias = bs; Kin = SDIM; }
    else             { inp = act + (size_t)(b*TT + t)*ADIM; W = Wa; bias = ba; Kin = ADIM; }

    int tid = threadIdx.x;
    if (tid < Kin) sIn[tid] = inp[tid];
    __syncthreads();

    int tsv = timesteps[b*TT + t];
    const float* te = temb + (size_t)tsv * HDIM;

    int c0 = 2*tid;
    float a0 = bias[c0] + te[c0], a1 = bias[c0+1] + te[c0+1];
    for (int k = 0; k < Kin; k++) {
        float x = sIn[k];
        a0 = fmaf(x, W[(size_t)k*HDIM + c0],     a0);
        a1 = fmaf(x, W[(size_t)k*HDIM + c0 + 1], a1);
    }
    float sum = blockReduceSum(a0 + a1, red);
    float m = sum * (1.0f / HDIM);
    float d0 = a0 - m, d1 = a1 - m;
    float ssq = blockReduceSum(d0*d0 + d1*d1, red);
    float rstd = rsqrtf(ssq * (1.0f / HDIM) + 1e-5f);
    float o0 = d0 * rstd * eg[c0]     + eb[c0];
    float o1 = d1 * rstd * eg[c0 + 1] + eb[c0 + 1];
    *(float2*)(out + (size_t)s*HDIM + c0) = make_float2(o0, o1);
    outs[(size_t)s*HPH + tid] = split2h(o0, o1);
}

// ============ tensor-core GEMM (fp16x2: A split, B single) ====================
// A: [M][K/2] uint2 (hi,lo fp16 pairs). B: [K/2][N] unsigned (fp16 pairs).
#define APAD 20
#define ASTG (128*APAD)

template<int BN>
__device__ __forceinline__ void tgemm_body(
    const uint2* __restrict__ A, const unsigned* __restrict__ B,
    const float* __restrict__ bias,
    float* __restrict__ C, uint2* __restrict__ Cs, unsigned* __restrict__ Cp,
    int M, int N, int K, int ep, float scl, char* smraw)
{
    constexpr int TNF = BN / 32;
    constexpr int BST = BN + 8;          // unsigned stride; ≡8 mod 32 -> conflict-free
    constexpr int BSTG = 16 * BST;
    uint2* Asm = (uint2*)smraw;
    unsigned* Bsm = (unsigned*)(Asm + 2*ASTG);

    const int tid  = threadIdx.x, lane = tid & 31, warp = tid >> 5;
    const int g    = lane >> 2,  tg   = lane & 3;
    const int wm0  = (warp >> 2) * 64, wn0 = (warp & 3) * (BN / 4);
    const int m0   = blockIdx.y * 128, n0 = blockIdx.x * BN;
    const int KW   = K >> 1;

    float acc[4][TNF][4];
    #pragma unroll
    for (int i = 0; i < 4; i++)
        #pragma unroll
        for (int j = 0; j < TNF; j++)
            #pragma unroll
            for (int l = 0; l < 4; l++) acc[i][j][l] = 0.f;

    const int T = K / 32;

    auto fill = [&](int t, int s) {
        uint2* Ad = Asm + s*ASTG;
        unsigned* Bd = Bsm + s*BSTG;
        int kw0 = t * 16;
        #pragma unroll
        for (int i = 0; i < 4; i++) {
            int id = tid + 256*i, r = id >> 3, c = (id & 7) * 2;
            cpa16(Ad + r*APAD + c, A + (size_t)(m0 + r)*KW + kw0 + c);
        }
        if (BN == 128) {
            #pragma unroll
            for (int i = 0; i < 2; i++) {
                int id = tid + 256*i, kp = id >> 5, nc = (id & 31) * 4;
                cpa16(Bd + kp*BST + nc, B + (size_t)(kw0 + kp)*N + n0 + nc);
            }
        } else {
            int kp = tid >> 4, nc = (tid & 15) * 4;
            cpa16(Bd + kp*BST + nc, B + (size_t)(kw0 + kp)*N + n0 + nc);
        }
        CP_COMMIT();
    };

    fill(0, 0);

    for (int t = 0; t < T; t++) {
        const int s = t & 1;
        CP_WAIT0();
        __syncthreads();
        if (t + 1 < T) fill(t + 1, s ^ 1);

        const uint2* As_ = Asm + s*ASTG;
        const unsigned* Bs_ = Bsm + s*BSTG;
        #pragma unroll
        for (int ks = 0; ks < 2; ks++) {
            const int kb = ks * 8;
            unsigned bf[TNF][2];
            #pragma unroll
            for (int tn = 0; tn < TNF; tn++) {
                int n = wn0 + tn*8 + g;
                bf[tn][0] = Bs_[(kb + tg)*BST + n];
                bf[tn][1] = Bs_[(kb + tg + 4)*BST + n];
            }
            #pragma unroll
            for (int tm = 0; tm < 4; tm++) {
                int m = wm0 + tm*16 + g;
                uint2 a0 = As_[m*APAD + kb + tg];
                uint2 a1 = As_[(m+8)*APAD + kb + tg];
                uint2 a2 = As_[m*APAD + kb + tg + 4];
                uint2 a3 = As_[(m+8)*APAD + kb + tg + 4];
                #pragma unroll
                for (int tn = 0; tn < TNF; tn++) {
                    mma16(acc[tm][tn], a0.x,a1.x,a2.x,a3.x, bf[tn][0], bf[tn][1]);
                    mma16(acc[tm][tn], a0.y,a1.y,a2.y,a3.y, bf[tn][0], bf[tn][1]);
                }
            }
        }
    }

    #pragma unroll
    for (int tm = 0; tm < 4; tm++) {
        #pragma unroll
        for (int tn = 0; tn < TNF; tn++) {
            int row = m0 + wm0 + tm*16 + g;
            int col = n0 + wn0 + tn*8 + tg*2;
            float b0v = bias[col], b1v = bias[col+1];
            float v00 = acc[tm][tn][0] + b0v, v01 = acc[tm][tn][1] + b1v;
            float v10 = acc[tm][tn][2] + b0v, v11 = acc[tm][tn][3] + b1v;
            if (ep == EP_BIAS) {
                *(float2*)(C + (size_t)row*N + col)     = make_float2(v00, v01);
                *(float2*)(C + (size_t)(row+8)*N + col) = make_float2(v10, v11);
            } else if (ep == EP_BIAS_PACK) {
                Cp[(size_t)row*(N>>1)     + (col>>1)] = pack2h(v00, v01);
                Cp[(size_t)(row+8)*(N>>1) + (col>>1)] = pack2h(v10, v11);
            } else {
                if (ep == EP_GELU_SPLIT) {
                    v00 = 0.5f*v00*(1.0f + erff(v00*0.70710678118654752f));
                    v01 = 0.5f*v01*(1.0f + erff(v01*0.70710678118654752f));
                    v10 = 0.5f*v10*(1.0f + erff(v10*0.70710678118654752f));
                    v11 = 0.5f*v11*(1.0f + erff(v11*0.70710678118654752f));
                } else {
                    v00 *= scl; v01 *= scl; v10 *= scl; v11 *= scl;
                }
                Cs[(size_t)row*(N>>1)     + (col>>1)] = split2h(v00, v01);
                Cs[(size_t)(row+8)*(N>>1) + (col>>1)] = split2h(v10, v11);
            }
        }
    }
}

template<int BN>
__global__ __launch_bounds__(256, 2) void tgemm_kernel(
    const uint2* __restrict__ A, const unsigned* __restrict__ B,
    const float* __restrict__ bias,
    float* __restrict__ C, uint2* __restrict__ Cs,
    int M, int N, int K, int ep)
{
    extern __shared__ char smraw[];
    tgemm_body<BN>(A, B, bias, C, Cs, nullptr, M, N, K, ep, 1.0f, smraw);
}

// ---------- split-K (2-way) GEMM, BN=64, 3-stage pipeline ---------------------
__global__ __launch_bounds__(256, 2) void tgemm_splitk_kernel(
    const uint2* __restrict__ A, const unsigned* __restrict__ B,
    float* __restrict__ P0, float* __restrict__ P1,
    int N, int K)
{
    constexpr int BN = 64, TNF = 2, BST = BN + 8, BSTG = 16 * BST;
    extern __shared__ char smraw[];
    uint2* Asm = (uint2*)smraw;
    unsigned* Bsm = (unsigned*)(Asm + 3*ASTG);

    const int tid  = threadIdx.x, lane = tid & 31, warp = tid >> 5;
    const int g    = lane >> 2,  tg   = lane & 3;
    const int wm0  = (warp >> 2) * 64, wn0 = (warp & 3) * 16;
    const int m0   = blockIdx.y * 128, n0 = blockIdx.x * BN;
    const int z    = blockIdx.z;
    const int KW   = K >> 1;
    const int kwb  = z * (KW >> 1);
    float* P = z ? P1 : P0;

    float acc[4][TNF][4];
    #pragma unroll
    for (int i = 0; i < 4; i++)
        #pragma unroll
        for (int j = 0; j < TNF; j++)
            #pragma unroll
            for (int l = 0; l < 4; l++) acc[i][j][l] = 0.f;

    const int T = (K / 2) / 32;

    auto fill = [&](int t, int s) {
        uint2* Ad = Asm + s*ASTG;
        unsigned* Bd = Bsm + s*BSTG;
        int kw0 = kwb + t * 16;
        #pragma unroll
        for (int i = 0; i < 4; i++) {
            int id = tid + 256*i, r = id >> 3, c = (id & 7) * 2;
            cpa16(Ad + r*APAD + c, A + (size_t)(m0 + r)*KW + kw0 + c);
        }
        int kp = tid >> 4, nc = (tid & 15) * 4;
        cpa16(Bd + kp*BST + nc, B + (size_t)(kw0 + kp)*N + n0 + nc);
        CP_COMMIT();
    };

    fill(0, 0);
    if (T > 1) fill(1, 1);

    for (int t = 0; t < T; t++) {
        const int s = t % 3;
        if (t + 1 < T) CP_WAIT1(); else CP_WAIT0();
        __syncthreads();
        if (t + 2 < T) fill(t + 2, (t + 2) % 3);

        const uint2* As_ = Asm + s*ASTG;
        const unsigned* Bs_ = Bsm + s*BSTG;
        #pragma unroll
        for (int ks = 0; ks < 2; ks++) {
            const int kb = ks * 8;
            unsigned bf[TNF][2];
            #pragma unroll
            for (int tn = 0; tn < TNF; tn++) {
                int n = wn0 + tn*8 + g;
                bf[tn][0] = Bs_[(kb + tg)*BST + n];
                bf[tn][1] = Bs_[(kb + tg + 4)*BST + n];
            }
            #pragma unroll
            for (int tm = 0; tm < 4; tm++) {
                int m = wm0 + tm*16 + g;
                uint2 a0 = As_[m*APAD + kb + tg];
                uint2 a1 = As_[(m+8)*APAD + kb + tg];
                uint2 a2 = As_[m*APAD + kb + tg + 4];
                uint2 a3 = As_[(m+8)*APAD + kb + tg + 4];
                #pragma unroll
                for (int tn = 0; tn < TNF; tn++) {
                    mma16(acc[tm][tn], a0.x,a1.x,a2.x,a3.x, bf[tn][0], bf[tn][1]);
                    mma16(acc[tm][tn], a0.y,a1.y,a2.y,a3.y, bf[tn][0], bf[tn][1]);
                }
            }
        }
    }

    #pragma unroll
    for (int tm = 0; tm < 4; tm++)
        #pragma unroll
        for (int tn = 0; tn < TNF; tn++) {
            int row = m0 + wm0 + tm*16 + g;
            int col = n0 + wn0 + tn*8 + tg*2;
            *(float2*)(P + (size_t)row*N + col)     = make_float2(acc[tm][tn][0], acc[tm][tn][1]);
            *(float2*)(P + (size_t)(row+8)*N + col) = make_float2(acc[tm][tn][2], acc[tm][tn][3]);
        }
}

// fused QKV: q split (scaled 1/8), k packed single, v fp32
__global__ __launch_bounds__(256, 2) void qkv_kernel(
    const uint2* __restrict__ hs,
    const unsigned* __restrict__ wq, const unsigned* __restrict__ wk, const unsigned* __restrict__ wv,
    const float* __restrict__ bq, const float* __restrict__ bk, const float* __restrict__ bv,
    uint2* __restrict__ qs, unsigned* __restrict__ ksp, float* __restrict__ v)
{
    extern __shared__ char smraw[];
    if (blockIdx.z == 0)
        tgemm_body<128>(hs, wq, bq, nullptr, qs, nullptr, MROWS, HDIM, HDIM, EP_BIAS_SPLIT, 0.125f, smraw);
    else if (blockIdx.z == 1)
        tgemm_body<128>(hs, wk, bk, nullptr, nullptr, ksp, MROWS, HDIM, HDIM, EP_BIAS_PACK, 1.0f, smraw);
    else
        tgemm_body<128>(hs, wv, bv, v, nullptr, nullptr, MROWS, HDIM, HDIM, EP_BIAS, 1.0f, smraw);
}

#define SM128  (2*(ASTG*(int)sizeof(uint2) + 16*136*(int)sizeof(unsigned)))
#define SM64_3 (3*(ASTG*(int)sizeof(uint2) + 16*72 *(int)sizeof(unsigned)))

// ================= flash attention (fp16x2) ====================================
#define FLASH_KPAD 136
#define FLASH_VPAD 72
#define FLASH_SMEM ((32*FLASH_KPAD + 64*FLASH_VPAD) * (int)sizeof(unsigned))

__global__ __launch_bounds__(256) void flash_kernel(
    const uint2* __restrict__ q, const unsigned* __restrict__ k,
    const float* __restrict__ v, uint2* __restrict__ ctxs)
{
    extern __shared__ unsigned dsm[];
    unsigned (*Ks)[FLASH_KPAD] = reinterpret_cast<unsigned(*)[FLASH_KPAD]>(dsm);
    unsigned (*Vs)[FLASH_VPAD] = reinterpret_cast<unsigned(*)[FLASH_VPAD]>(dsm + 32*FLASH_KPAD);

    const int it = (int)(gridDim.x - 1 - blockIdx.x);
    const int bh = blockIdx.y, b = bh >> 3, h = bh & 7;
    const uint2*    qb = q + (size_t)b*SS*HPH + h*32;
    const unsigned* kb = k + (size_t)b*SS*HPH + h*32;
    const float*    vb = v + (size_t)b*SS*HDIM + h*DH;
    uint2*          cb = ctxs + (size_t)b*SS*HPH + h*32;

    const int tid  = threadIdx.x, lane = tid & 31, warp = tid >> 5;
    const int g    = lane >> 2,  tg   = lane & 3;
    const int i0   = it * 128;
    const int rowg = i0 + warp*16 + g;

    uint2 qf[4][4];
    {
        const uint2* qrg = qb + (size_t)rowg*HPH;
        const uint2* qr8 = qrg + 8*HPH;
        #pragma unroll
        for (int kk = 0; kk < 4; kk++) {
            qf[kk][0] = qrg[kk*8 + tg];
            qf[kk][1] = qr8[kk*8 + tg];
            qf[kk][2] = qrg[kk*8 + tg + 4];
            qf[kk][3] = qr8[kk*8 + tg + 4];
        }
    }

    float m0 = -1e30f, m1 = -1e30f, l0 = 0.f, l1 = 0.f;
    float o[8][4];
    #pragma unroll
    for (int nf = 0; nf < 8; nf++)
        #pragma unroll
        for (int l = 0; l < 4; l++) o[nf][l] = 0.f;

    const int kjr = tid >> 1, kcb = (tid & 1)*16;
    const int vjp = tid >> 2, vcb = (tid & 3)*16;

    for (int jt = 0; jt <= it; jt++) {
        const int j0 = jt * 128;
        {
            const unsigned* krow = kb + (size_t)(j0 + kjr)*HPH + kcb;
            #pragma unroll
            for (int u = 0; u < 4; u++) {
                uint4 f = ((const uint4*)krow)[u];
                Ks[kcb + 4*u + 0][kjr] = f.x;
                Ks[kcb + 4*u + 1][kjr] = f.y;
                Ks[kcb + 4*u + 2][kjr] = f.z;
                Ks[kcb + 4*u + 3][kjr] = f.w;
            }
        }
        {
            const float* vr0 = vb + (size_t)(j0 + 2*vjp)*HDIM + vcb;
            const float* vr1 = vr0 + HDIM;
            #pragma unroll
            for (int u = 0; u < 4; u++) {
                float4 f0 = *(const float4*)(vr0 + u*4);
                float4 f1 = *(const float4*)(vr1 + u*4);
                Vs[vjp][vcb + u*4 + 0] = pack2h(f0.x, f1.x);
                Vs[vjp][vcb + u*4 + 1] = pack2h(f0.y, f1.y);
                Vs[vjp][vcb + u*4 + 2] = pack2h(f0.z, f1.z);
                Vs[vjp][vcb + u*4 + 3] = pack2h(f0.w, f1.w);
            }
        }
        __syncthreads();

        float s[16][4];
        #pragma unroll
        for (int jf = 0; jf < 16; jf++)
            #pragma unroll
            for (int l = 0; l < 4; l++) s[jf][l] = 0.f;

        #pragma unroll
        for (int kk = 0; kk < 4; kk++) {
            uint2 a0 = qf[kk][0], a1 = qf[kk][1], a2 = qf[kk][2], a3 = qf[kk][3];
            #pragma unroll
            for (int jf = 0; jf < 16; jf++) {
                unsigned b0 = Ks[kk*8 + tg][jf*8 + g];
                unsigned b1 = Ks[kk*8 + tg + 4][jf*8 + g];
                mma16(s[jf], a0.x,a1.x,a2.x,a3.x, b0, b1);
                mma16(s[jf], a0.y,a1.y,a2.y,a3.y, b0, b1);
            }
        }

        if (jt == it) {
            const int r0 = warp*16 + g, r1 = r0 + 8;
            #pragma unroll
            for (int jf = 0; jf < 16; jf++) {
                int c0 = jf*8 + 2*tg;
                if (c0     > r0) s[jf][0] = -1e30f;
                if (c0 + 1 > r0) s[jf][1] = -1e30f;
                if (c0     > r1) s[jf][2] = -1e30f;
                if (c0 + 1 > r1) s[jf][3] = -1e30f;
            }
        }

        float tm0 = -1e30f, tm1 = -1e30f;
        #pragma unroll
        for (int jf = 0; jf < 16; jf++) {
            tm0 = fmaxf(tm0, fmaxf(s[jf][0], s[jf][1]));
            tm1 = fmaxf(tm1, fmaxf(s[jf][2], s[jf][3]));
        }
        tm0 = fmaxf(tm0, __shfl_xor_sync(0xffffffffu, tm0, 1));
        tm0 = fmaxf(tm0, __shfl_xor_sync(0xffffffffu, tm0, 2));
        tm1 = fmaxf(tm1, __shfl_xor_sync(0xffffffffu, tm1, 1));
        tm1 = fmaxf(tm1, __shfl_xor_sync(0xffffffffu, tm1, 2));

        float nm0 = fmaxf(m0, tm0), nm1 = fmaxf(m1, tm1);
        float al0 = __expf(m0 - nm0), al1 = __expf(m1 - nm1);
        m0 = nm0; m1 = nm1;

        float rs0 = 0.f, rs1 = 0.f;
        #pragma unroll
        for (int jf = 0; jf < 16; jf++) {
            s[jf][0] = __expf(s[jf][0] - nm0);
            s[jf][1] = __expf(s[jf][1] - nm0);
            s[jf][2] = __expf(s[jf][2] - nm1);
            s[jf][3] = __expf(s[jf][3] - nm1);
            rs0 += s[jf][0] + s[jf][1];
            rs1 += s[jf][2] + s[jf][3];
        }
        rs0 += __shfl_xor_sync(0xffffffffu, rs0, 1);
        rs0 += __shfl_xor_sync(0xffffffffu, rs0, 2);
        rs1 += __shfl_xor_sync(0xffffffffu, rs1, 1);
        rs1 += __shfl_xor_sync(0xffffffffu, rs1, 2);
        l0 = l0*al0 + rs0;
        l1 = l1*al1 + rs1;

        #pragma unroll
        for (int nf = 0; nf < 8; nf++) {
            o[nf][0] *= al0; o[nf][1] *= al0;
            o[nf][2] *= al1; o[nf][3] *= al1;
        }

        #pragma unroll
        for (int kk = 0; kk < 8; kk++) {
            uint2 A0 = split2h(s[2*kk][0],   s[2*kk][1]);
            uint2 A1 = split2h(s[2*kk][2],   s[2*kk][3]);
            uint2 A2 = split2h(s[2*kk+1][0], s[2*kk+1][1]);
            uint2 A3 = split2h(s[2*kk+1][2], s[2*kk+1][3]);
            #pragma unroll
            for (int nf = 0; nf < 8; nf++) {
                unsigned b0 = Vs[kk*8 + tg][nf*8 + g];
                unsigned b1 = Vs[kk*8 + tg + 4][nf*8 + g];
                mma16(o[nf], A0.x,A1.x,A2.x,A3.x, b0, b1);
                mma16(o[nf], A0.y,A1.y,A2.y,A3.y, b0, b1);
            }
        }
        __syncthreads();
    }

    float inv0 = 1.0f / l0, inv1 = 1.0f / l1;
    uint2* crow0 = cb + (size_t)rowg*HPH;
    uint2* crow1 = crow0 + 8*HPH;
    #pragma unroll
    for (int nf = 0; nf < 8; nf++) {
        crow0[nf*4 + tg] = split2h(o[nf][0]*inv0, o[nf][1]*inv0);
        crow1[nf*4 + tg] = split2h(o[nf][2]*inv1, o[nf][3]*inv1);
    }
}

// ---------- layernorm over (p0 + p1 + bias + res): warp-per-row ---------------
__global__ __launch_bounds__(256) void ln_sum_kernel(
    const float* __restrict__ p0, const float* __restrict__ p1,
    const float* __restrict__ bias, const float* __restrict__ res,
    const float* __restrict__ g, const float* __restrict__ b,
    float* __restrict__ out, uint2* __restrict__ outs)
{
    int row  = blockIdx.x * 8 + (threadIdx.x >> 5);
    int lane = threadIdx.x & 31;
    const float* p0r = p0 + (size_t)row * HDIM;
    const float* p1r = p1 + (size_t)row * HDIM;
    const float* rr  = res + (size_t)row * HDIM;

    float4 xv[4];
    float sum = 0.f;
    #pragma unroll
    for (int i = 0; i < 4; i++) {
        int c = lane*4 + i*128;
        float4 a = *(const float4*)(p0r + c);
        float4 d = *(const float4*)(p1r + c);
        float4 e = *(const float4*)(bias + c);
        float4 f = *(const float4*)(rr + c);
        xv[i].x = a.x + d.x + e.x + f.x;
        xv[i].y = a.y + d.y + e.y + f.y;
        xv[i].z = a.z + d.z + e.z + f.z;
        xv[i].w = a.w + d.w + e.w + f.w;
        sum += (xv[i].x + xv[i].y) + (xv[i].z + xv[i].w);
    }
    #pragma unroll
    for (int o = 16; o; o >>= 1) sum += __shfl_xor_sync(0xffffffffu, sum, o);
    float m = sum * (1.0f / HDIM);

    float ssq = 0.f;
    #pragma unroll
    for (int i = 0; i < 4; i++) {
        xv[i].x -= m; xv[i].y -= m; xv[i].z -= m; xv[i].w -= m;
        ssq += xv[i].x*xv[i].x + xv[i].y*xv[i].y + xv[i].z*xv[i].z + xv[i].w*xv[i].w;
    }
    #pragma unroll
    for (int o = 16; o; o >>= 1) ssq += __shfl_xor_sync(0xffffffffu, ssq, o);
    float rstd = rsqrtf(ssq * (1.0f / HDIM) + 1e-5f);

    float* outr = out + (size_t)row * HDIM;
    uint2* outsr = outs + (size_t)row * HPH;
    #pragma unroll
    for (int i = 0; i < 4; i++) {
        int c = lane*4 + i*128;
        float4 gv = *(const float4*)(g + c);
        float4 bv = *(const float4*)(b + c);
        float4 ov;
        ov.x = xv[i].x * rstd * gv.x + bv.x;
        ov.y = xv[i].y * rstd * gv.y + bv.y;
        ov.z = xv[i].z * rstd * gv.z + bv.z;
        ov.w = xv[i].w * rstd * gv.w + bv.w;
        *(float4*)(outr + c) = ov;
        outsr[(c >> 1)    ] = split2h(ov.x, ov.y);
        outsr[(c >> 1) + 1] = split2h(ov.z, ov.w);
    }
}

// ---------------- final projection ----------------
__global__ __launch_bounds__(256) void final_kernel(
    const float* __restrict__ h, const float* __restrict__ Wp,
    const float* __restrict__ bp, float* __restrict__ out)
{
    int bt = blockIdx.x;
    int b = bt / TT, t = bt % TT;
    const float* row = h + ((size_t)b*SS + 3*t + 1) * HDIM;
    __shared__ float sRow[HDIM];
    __shared__ float part[8][ADIM];
    int tid = threadIdx.x;
    sRow[tid] = row[tid];
    sRow[tid + 256] = row[tid + 256];
    __syncthreads();
    int c = tid & 31, g = tid >> 5;
    float a = 0.f;
    for (int k = g*64; k < (g+1)*64; k++) a = fmaf(sRow[k], Wp[(size_t)k*ADIM + c], a);
    part[g][c] = a;
    __syncthreads();
    if (tid < ADIM) {
        float s = bp[tid];
        #pragma unroll
        for (int g2 = 0; g2 < 8; g2++) s += part[g2][tid];
        out[(size_t)bt*ADIM + tid] = s;
    }
}

// ---------------- driver ----------------
extern "C" void kernel_launch(void* const* d_in, const int* in_sizes, int n_in,
                              void* d_out, int out_size)
{
    const int*   timesteps = (const int*)  d_in[0];
    const float* state_0   = (const float*)d_in[1];
    const float* state_1   = (const float*)d_in[2];
    const float* actions   = (const float*)d_in[3];
    const float* time_emb  = (const float*)d_in[4];
    const float* Ws  = (const float*)d_in[5];
    const float* bs  = (const float*)d_in[6];
    const float* Wa  = (const float*)d_in[7];
    const float* ba  = (const float*)d_in[8];
    const float* Wq  = (const float*)d_in[9];
    const float* bq  = (const float*)d_in[10];
    const float* Wk  = (const float*)d_in[11];
    const float* bk  = (const float*)d_in[12];
    const float* Wv  = (const float*)d_in[13];
    const float* bv  = (const float*)d_in[14];
    const float* Wo  = (const float*)d_in[15];
    const float* bo  = (const float*)d_in[16];
    const float* W1  = (const float*)d_in[17];
    const float* b1  = (const float*)d_in[18];
    const float* W2  = (const float*)d_in[19];
    const float* b2  = (const float*)d_in[20];
    const float* ln1_g = (const float*)d_in[21];
    const float* ln1_b = (const float*)d_in[22];
    const float* ln2_g = (const float*)d_in[23];
    const float* ln2_b = (const float*)d_in[24];
    const float* eln_g = (const float*)d_in[25];
    const float* eln_b = (const float*)d_in[26];
    const float* Wp  = (const float*)d_in[27];
    const float* bp  = (const float*)d_in[28];

    float *h, *v, *p0, *p1, *ln1o;
    uint2 *hs, *qs, *ctxs, *ln1s, *mlps;
    unsigned *ksp, *ws;
    cudaGetSymbolAddress((void**)&h,    g_h);
    cudaGetSymbolAddress((void**)&v,    g_v);
    cudaGetSymbolAddress((void**)&p0,   g_p0);
    cudaGetSymbolAddress((void**)&p1,   g_p1);
    cudaGetSymbolAddress((void**)&ln1o, g_ln1);
    cudaGetSymbolAddress((void**)&hs,   g_hs);
    cudaGetSymbolAddress((void**)&qs,   g_qs);
    cudaGetSymbolAddress((void**)&ksp,  g_ksp);
    cudaGetSymbolAddress((void**)&ctxs, g_ctxs);
    cudaGetSymbolAddress((void**)&ln1s, g_ln1s);
    cudaGetSymbolAddress((void**)&mlps, g_mlps);
    cudaGetSymbolAddress((void**)&ws,   g_ws);

    cudaFuncSetAttribute(flash_kernel,
                         cudaFuncAttributeMaxDynamicSharedMemorySize, FLASH_SMEM);
    cudaFuncSetAttribute(tgemm_kernel<128>,
                         cudaFuncAttributeMaxDynamicSharedMemorySize, SM128);
    cudaFuncSetAttribute(tgemm_splitk_kernel,
                         cudaFuncAttributeMaxDynamicSharedMemorySize, SM64_3);
    cudaFuncSetAttribute(qkv_kernel,
                         cudaFuncAttributeMaxDynamicSharedMemorySize, SM128);

    wsplit_kernel<<<dim3(HDIM/256, NBLK*HDIM/2), 256>>>(Wq, ws + WQ0, HDIM);
    wsplit_kernel<<<dim3(HDIM/256, NBLK*HDIM/2), 256>>>(Wk, ws + WK0, HDIM);
    wsplit_kernel<<<dim3(HDIM/256, NBLK*HDIM/2), 256>>>(Wv, ws + WV0, HDIM);
    wsplit_kernel<<<dim3(HDIM/256, NBLK*HDIM/2), 256>>>(Wo, ws + WO0, HDIM);
    wsplit_kernel<<<dim3(DFF/256,  NBLK*HDIM/2), 256>>>(W1, ws + W10, DFF);
    wsplit_kernel<<<dim3(HDIM/256, NBLK*DFF/2),  256>>>(W2, ws + W20, HDIM);

    embed_kernel<<<BB*SS, 256>>>(timesteps, state_0, state_1, actions, time_emb,
                                 Ws, bs, Wa, ba, eln_g, eln_b, h, hs);

    dim3 gQKV(HDIM/128, MROWS/128, 3);   // (4, 48, 3)
    dim3 gSK (HDIM/64,  MROWS/128, 2);   // (8, 48, 2)
    dim3 gF  (DFF /128, MROWS/128);      // (16, 48)
    dim3 gFl (SS/128, BB*NH);            // (12, 32)

    for (int blk = 0; blk < NBLK; blk++) {
        const unsigned* wqs = ws + WQ0 + (size_t)blk*131072;
        const unsigned* wks = ws + WK0 + (size_t)blk*131072;
        const unsigned* wvs = ws + WV0 + (size_t)blk*131072;
        const unsigned* wos = ws + WO0 + (size_t)blk*131072;
        const unsigned* w1s = ws + W10 + (size_t)blk*524288;
        const unsigned* w2s = ws + W20 + (size_t)blk*524288;
        const float* bq_ = bq + (size_t)blk*HDIM;
        const float* bk_ = bk + (size_t)blk*HDIM;
        const float* bv_ = bv + (size_t)blk*HDIM;
        const float* bo_ = bo + (size_t)blk*HDIM;
        const float* b1_ = b1 + (size_t)blk*DFF;
        const float* b2_ = b2 + (size_t)blk*HDIM;
        const float* g1_ = ln1_g + (size_t)blk*HDIM;
        const float* e1_ = ln1_b + (size_t)blk*HDIM;
        const float* g2_ = ln2_g + (size_t)blk*HDIM;
        const float* e2_ = ln2_b + (size_t)blk*HDIM;

        qkv_kernel<<<gQKV, 256, SM128>>>(hs, wqs, wks, wvs, bq_, bk_, bv_, qs, ksp, v);

        flash_kernel<<<gFl, 256, FLASH_SMEM>>>(qs, ksp, v, ctxs);

        tgemm_splitk_kernel<<<gSK, 256, SM64_3>>>(ctxs, wos, p0, p1, HDIM, HDIM);
        ln_sum_kernel<<<MROWS/8, 256>>>(p0, p1, bo_, h, g1_, e1_, ln1o, ln1s);
        tgemm_kernel<128><<<gF, 256, SM128>>>(ln1s, w1s, b1_, nullptr, mlps,
                                              MROWS, DFF, HDIM, EP_GELU_SPLIT);
        tgemm_splitk_kernel<<<gSK, 256, SM64_3>>>(mlps, w2s, p0, p1, HDIM, DFF);
        ln_sum_kernel<<<MROWS/8, 256>>>(p0, p1, b2_, ln1o, g2_, e2_, h, hs);
    }

    final_kernel<<<BB*TT, 256>>>(h, Wp, bp, (float*)d_out);
}

// round 16
// speedup vs baseline: 2.2354x; 1.4159x over previous
#include <cuda_runtime.h>
#include <cuda_fp16.h>
#include <math.h>

#define BB 4
#define TT 512
#define SS 1536
#define SDIM 64
#define ADIM 32
#define HDIM 512
#define HPH 256
#define NH 8
#define DH 64
#define NBLK 6
#define DFFH 1024
#define DFF 2048
#define MROWS (BB*SS)

enum { EP_BIAS = 0, EP_GELU_PACK = 2, EP_BIAS_PACK = 4 };

// ---------------- scratch ----------------
__device__ float g_h  [MROWS * HDIM];
__device__ float g_v  [MROWS * HDIM];
__device__ float g_p0 [MROWS * HDIM];
__device__ float g_p1 [MROWS * HDIM];
__device__ float g_ln1[MROWS * HDIM];

__device__ unsigned g_hs  [MROWS * HPH];   // all activations: single fp16 pairs
__device__ unsigned g_qs  [MROWS * HPH];
__device__ unsigned g_ksp [MROWS * HPH];
__device__ unsigned g_ctxs[MROWS * HPH];
__device__ unsigned g_ln1s[MROWS * HPH];
__device__ unsigned g_mlps[MROWS * DFFH];

// weight planes: single fp16 pairs [blk][k/2][n]
#define WQ0 0
#define WK0 786432
#define WV0 1572864
#define WO0 2359296
#define W10 3145728
#define W20 6291456
__device__ unsigned g_ws[9437184];

// ---------------- fp16 helpers ----------------
__device__ __forceinline__ unsigned pack2h(float x0, float x1) {
    __half2 hh = __floats2half2_rn(x0, x1);
    return *reinterpret_cast<unsigned*>(&hh);
}

__device__ __forceinline__ void mma16(float c[4],
    unsigned a0, unsigned a1, unsigned a2, unsigned a3,
    unsigned b0, unsigned b1)
{
    asm volatile(
      "mma.sync.aligned.m16n8k16.row.col.f32.f16.f16.f32 "
      "{%0,%1,%2,%3},{%4,%5,%6,%7},{%8,%9},{%0,%1,%2,%3};"
      : "+f"(c[0]), "+f"(c[1]), "+f"(c[2]), "+f"(c[3])
      : "r"(a0), "r"(a1), "r"(a2), "r"(a3), "r"(b0), "r"(b1));
}

__device__ __forceinline__ void cpa16(void* s, const void* g) {
    unsigned a = (unsigned)__cvta_generic_to_shared(s);
    asm volatile("cp.async.cg.shared.global [%0], [%1], 16;" :: "r"(a), "l"(g));
}
#define CP_COMMIT() asm volatile("cp.async.commit_group;")
#define CP_WAIT0()  asm volatile("cp.async.wait_group 0;")
#define CP_WAIT1()  asm volatile("cp.async.wait_group 1;")

// ---------------- reductions ----------------
__device__ __forceinline__ float blockReduceSum(float v, float* sm) {
    int lane = threadIdx.x & 31, wid = threadIdx.x >> 5;
    #pragma unroll
    for (int o = 16; o; o >>= 1) v += __shfl_down_sync(0xffffffffu, v, o);
    if (lane == 0) sm[wid] = v;
    __syncthreads();
    float r = 0.f;
    if (wid == 0) {
        r = (lane < 8) ? sm[lane] : 0.f;
        #pragma unroll
        for (int o = 4; o; o >>= 1) r += __shfl_down_sync(0xffffffffu, r, o);
        if (lane == 0) sm[0] = r;
    }
    __syncthreads();
    r = sm[0];
    __syncthreads();
    return r;
}

// ---------------- weight pack: W[k][n] -> Wp[k/2][n] fp16 pairs --------------
__global__ __launch_bounds__(256) void wsplit_kernel(
    const float* __restrict__ src, unsigned* __restrict__ dst, int N)
{
    int n  = blockIdx.x * 256 + threadIdx.x;
    int kp = blockIdx.y;
    dst[(size_t)kp * N + n] =
        pack2h(src[(size_t)(2*kp) * N + n], src[(size_t)(2*kp + 1) * N + n]);
}

// ---------------- embedding + eLN ----------------
__global__ __launch_bounds__(256) void embed_kernel(
    const int* __restrict__ timesteps, const float* __restrict__ s0,
    const float* __restrict__ s1, const float* __restrict__ act,
    const float* __restrict__ temb,
    const float* __restrict__ Ws, const float* __restrict__ bs,
    const float* __restrict__ Wa, const float* __restrict__ ba,
    const float* __restrict__ eg, const float* __restrict__ eb,
    float* __restrict__ out, unsigned* __restrict__ outs)
{
    int s = blockIdx.x;
    int b = s / SS, sr = s % SS;
    int t = sr / 3, r = sr % 3;

    __shared__ float sIn[SDIM];
    __shared__ float red[32];

    const float* inp; const float* W; const float* bias; int Kin;
    if (r == 0)      { inp = s0  + (size_t)(b*TT + t)*SDIM; W = Ws; bias = bs; Kin = SDIM; }
    else if (r == 1) { inp = s1  + (size_t)(b*TT + t)*SDIM; W = Ws; bias = bs; Kin = SDIM; }
    else             { inp = act + (size_t)(b*TT + t)*ADIM; W = Wa; bias = ba; Kin = ADIM; }

    int tid = threadIdx.x;
    if (tid < Kin) sIn[tid] = inp[tid];
    __syncthreads();

    int tsv = timesteps[b*TT + t];
    const float* te = temb + (size_t)tsv * HDIM;

    int c0 = 2*tid;
    float a0 = bias[c0] + te[c0], a1 = bias[c0+1] + te[c0+1];
    for (int k = 0; k < Kin; k++) {
        float x = sIn[k];
        a0 = fmaf(x, W[(size_t)k*HDIM + c0],     a0);
        a1 = fmaf(x, W[(size_t)k*HDIM + c0 + 1], a1);
    }
    float sum = blockReduceSum(a0 + a1, red);
    float m = sum * (1.0f / HDIM);
    float d0 = a0 - m, d1 = a1 - m;
    float ssq = blockReduceSum(d0*d0 + d1*d1, red);
    float rstd = rsqrtf(ssq * (1.0f / HDIM) + 1e-5f);
    float o0 = d0 * rstd * eg[c0]     + eb[c0];
    float o1 = d1 * rstd * eg[c0 + 1] + eb[c0 + 1];
    *(float2*)(out + (size_t)s*HDIM + c0) = make_float2(o0, o1);
    outs[(size_t)s*HPH + tid] = pack2h(o0, o1);
}

// ============ tensor-core GEMM (fp16 single both sides) =======================
// A: [M][K/2] unsigned. B: [K/2][N] unsigned. 1 mma per k-step.
#define APAD 20
#define ASTG (128*APAD)     // unsigned units

template<int BN>
__device__ __forceinline__ void tgemm_body(
    const unsigned* __restrict__ A, const unsigned* __restrict__ B,
    const float* __restrict__ bias,
    float* __restrict__ C, unsigned* __restrict__ Cp,
    int M, int N, int K, int ep, float scl, char* smraw)
{
    constexpr int TNF = BN / 32;
    constexpr int BST = BN + 8;
    constexpr int BSTG = 16 * BST;
    unsigned* Asm = (unsigned*)smraw;
    unsigned* Bsm = Asm + 2*ASTG;

    const int tid  = threadIdx.x, lane = tid & 31, warp = tid >> 5;
    const int g    = lane >> 2,  tg   = lane & 3;
    const int wm0  = (warp >> 2) * 64, wn0 = (warp & 3) * (BN / 4);
    const int m0   = blockIdx.y * 128, n0 = blockIdx.x * BN;
    const int KW   = K >> 1;

    float acc[4][TNF][4];
    #pragma unroll
    for (int i = 0; i < 4; i++)
        #pragma unroll
        for (int j = 0; j < TNF; j++)
            #pragma unroll
            for (int l = 0; l < 4; l++) acc[i][j][l] = 0.f;

    const int T = K / 32;

    auto fill = [&](int t, int s) {
        unsigned* Ad = Asm + s*ASTG;
        unsigned* Bd = Bsm + s*BSTG;
        int kw0 = t * 16;
        #pragma unroll
        for (int i = 0; i < 2; i++) {
            int id = tid + 256*i, r = id >> 2, c = (id & 3) * 4;
            cpa16(Ad + r*APAD + c, A + (size_t)(m0 + r)*KW + kw0 + c);
        }
        if (BN == 128) {
            #pragma unroll
            for (int i = 0; i < 2; i++) {
                int id = tid + 256*i, kp = id >> 5, nc = (id & 31) * 4;
                cpa16(Bd + kp*BST + nc, B + (size_t)(kw0 + kp)*N + n0 + nc);
            }
        } else {
            int kp = tid >> 4, nc = (tid & 15) * 4;
            cpa16(Bd + kp*BST + nc, B + (size_t)(kw0 + kp)*N + n0 + nc);
        }
        CP_COMMIT();
    };

    fill(0, 0);

    for (int t = 0; t < T; t++) {
        const int s = t & 1;
        CP_WAIT0();
        __syncthreads();
        if (t + 1 < T) fill(t + 1, s ^ 1);

        const unsigned* As_ = Asm + s*ASTG;
        const unsigned* Bs_ = Bsm + s*BSTG;
        #pragma unroll
        for (int ks = 0; ks < 2; ks++) {
            const int kb = ks * 8;
            unsigned bf[TNF][2];
            #pragma unroll
            for (int tn = 0; tn < TNF; tn++) {
                int n = wn0 + tn*8 + g;
                bf[tn][0] = Bs_[(kb + tg)*BST + n];
                bf[tn][1] = Bs_[(kb + tg + 4)*BST + n];
            }
            #pragma unroll
            for (int tm = 0; tm < 4; tm++) {
                int m = wm0 + tm*16 + g;
                unsigned a0 = As_[m*APAD + kb + tg];
                unsigned a1 = As_[(m+8)*APAD + kb + tg];
                unsigned a2 = As_[m*APAD + kb + tg + 4];
                unsigned a3 = As_[(m+8)*APAD + kb + tg + 4];
                #pragma unroll
                for (int tn = 0; tn < TNF; tn++)
                    mma16(acc[tm][tn], a0, a1, a2, a3, bf[tn][0], bf[tn][1]);
            }
        }
    }

    #pragma unroll
    for (int tm = 0; tm < 4; tm++) {
        #pragma unroll
        for (int tn = 0; tn < TNF; tn++) {
            int row = m0 + wm0 + tm*16 + g;
            int col = n0 + wn0 + tn*8 + tg*2;
            float b0v = bias[col], b1v = bias[col+1];
            float v00 = acc[tm][tn][0] + b0v, v01 = acc[tm][tn][1] + b1v;
            float v10 = acc[tm][tn][2] + b0v, v11 = acc[tm][tn][3] + b1v;
            if (ep == EP_BIAS) {
                *(float2*)(C + (size_t)row*N + col)     = make_float2(v00, v01);
                *(float2*)(C + (size_t)(row+8)*N + col) = make_float2(v10, v11);
            } else {
                if (ep == EP_GELU_PACK) {
                    v00 = 0.5f*v00*(1.0f + erff(v00*0.70710678118654752f));
                    v01 = 0.5f*v01*(1.0f + erff(v01*0.70710678118654752f));
                    v10 = 0.5f*v10*(1.0f + erff(v10*0.70710678118654752f));
                    v11 = 0.5f*v11*(1.0f + erff(v11*0.70710678118654752f));
                } else {
                    v00 *= scl; v01 *= scl; v10 *= scl; v11 *= scl;
                }
                Cp[(size_t)row*(N>>1)     + (col>>1)] = pack2h(v00, v01);
                Cp[(size_t)(row+8)*(N>>1) + (col>>1)] = pack2h(v10, v11);
            }
        }
    }
}

template<int BN>
__global__ __launch_bounds__(256, 2) void tgemm_kernel(
    const unsigned* __restrict__ A, const unsigned* __restrict__ B,
    const float* __restrict__ bias,
    float* __restrict__ C, unsigned* __restrict__ Cp,
    int M, int N, int K, int ep)
{
    extern __shared__ char smraw[];
    tgemm_body<BN>(A, B, bias, C, Cp, M, N, K, ep, 1.0f, smraw);
}

// ---------- split-K (2-way) GEMM, BN=64, 3-stage pipeline ---------------------
__global__ __launch_bounds__(256, 2) void tgemm_splitk_kernel(
    const unsigned* __restrict__ A, const unsigned* __restrict__ B,
    float* __restrict__ P0, float* __restrict__ P1,
    int N, int K)
{
    constexpr int BN = 64, TNF = 2, BST = BN + 8, BSTG = 16 * BST;
    extern __shared__ char smraw[];
    unsigned* Asm = (unsigned*)smraw;
    unsigned* Bsm = Asm + 3*ASTG;

    const int tid  = threadIdx.x, lane = tid & 31, warp = tid >> 5;
    const int g    = lane >> 2,  tg   = lane & 3;
    const int wm0  = (warp >> 2) * 64, wn0 = (warp & 3) * 16;
    const int m0   = blockIdx.y * 128, n0 = blockIdx.x * BN;
    const int z    = blockIdx.z;
    const int KW   = K >> 1;
    const int kwb  = z * (KW >> 1);
    float* P = z ? P1 : P0;

    float acc[4][TNF][4];
    #pragma unroll
    for (int i = 0; i < 4; i++)
        #pragma unroll
        for (int j = 0; j < TNF; j++)
            #pragma unroll
            for (int l = 0; l < 4; l++) acc[i][j][l] = 0.f;

    const int T = (K / 2) / 32;

    auto fill = [&](int t, int s) {
        unsigned* Ad = Asm + s*ASTG;
        unsigned* Bd = Bsm + s*BSTG;
        int kw0 = kwb + t * 16;
        #pragma unroll
        for (int i = 0; i < 2; i++) {
            int id = tid + 256*i, r = id >> 2, c = (id & 3) * 4;
            cpa16(Ad + r*APAD + c, A + (size_t)(m0 + r)*KW + kw0 + c);
        }
        int kp = tid >> 4, nc = (tid & 15) * 4;
        cpa16(Bd + kp*BST + nc, B + (size_t)(kw0 + kp)*N + n0 + nc);
        CP_COMMIT();
    };

    fill(0, 0);
    if (T > 1) fill(1, 1);

    for (int t = 0; t < T; t++) {
        const int s = t % 3;
        if (t + 1 < T) CP_WAIT1(); else CP_WAIT0();
        __syncthreads();
        if (t + 2 < T) fill(t + 2, (t + 2) % 3);

        const unsigned* As_ = Asm + s*ASTG;
        const unsigned* Bs_ = Bsm + s*BSTG;
        #pragma unroll
        for (int ks = 0; ks < 2; ks++) {
            const int kb = ks * 8;
            unsigned bf[TNF][2];
            #pragma unroll
            for (int tn = 0; tn < TNF; tn++) {
                int n = wn0 + tn*8 + g;
                bf[tn][0] = Bs_[(kb + tg)*BST + n];
                bf[tn][1] = Bs_[(kb + tg + 4)*BST + n];
            }
            #pragma unroll
            for (int tm = 0; tm < 4; tm++) {
                int m = wm0 + tm*16 + g;
                unsigned a0 = As_[m*APAD + kb + tg];
                unsigned a1 = As_[(m+8)*APAD + kb + tg];
                unsigned a2 = As_[m*APAD + kb + tg + 4];
                unsigned a3 = As_[(m+8)*APAD + kb + tg + 4];
                #pragma unroll
                for (int tn = 0; tn < TNF; tn++)
                    mma16(acc[tm][tn], a0, a1, a2, a3, bf[tn][0], bf[tn][1]);
            }
        }
    }

    #pragma unroll
    for (int tm = 0; tm < 4; tm++)
        #pragma unroll
        for (int tn = 0; tn < TNF; tn++) {
            int row = m0 + wm0 + tm*16 + g;
            int col = n0 + wn0 + tn*8 + tg*2;
            *(float2*)(P + (size_t)row*N + col)     = make_float2(acc[tm][tn][0], acc[tm][tn][1]);
            *(float2*)(P + (size_t)(row+8)*N + col) = make_float2(acc[tm][tn][2], acc[tm][tn][3]);
        }
}

// fused QKV: q packed (scaled 1/8), k packed, v fp32
__global__ __launch_bounds__(256, 2) void qkv_kernel(
    const unsigned* __restrict__ hs,
    const unsigned* __restrict__ wq, const unsigned* __restrict__ wk, const unsigned* __restrict__ wv,
    const float* __restrict__ bq, const float* __restrict__ bk, const float* __restrict__ bv,
    unsigned* __restrict__ qs, unsigned* __restrict__ ksp, float* __restrict__ v)
{
    extern __shared__ char smraw[];
    if (blockIdx.z == 0)
        tgemm_body<128>(hs, wq, bq, nullptr, qs, MROWS, HDIM, HDIM, EP_BIAS_PACK, 0.125f, smraw);
    else if (blockIdx.z == 1)
        tgemm_body<128>(hs, wk, bk, nullptr, ksp, MROWS, HDIM, HDIM, EP_BIAS_PACK, 1.0f, smraw);
    else
        tgemm_body<128>(hs, wv, bv, v, nullptr, MROWS, HDIM, HDIM, EP_BIAS, 1.0f, smraw);
}

#define SM128  (2*(ASTG + 16*136)*(int)sizeof(unsigned))
#define SM64_3 (3*(ASTG + 16*72 )*(int)sizeof(unsigned))

// ================= flash attention (fp16 single both operands) =================
#define FLASH_KPAD 136
#define FLASH_VPAD 72
#define FLASH_SMEM ((32*FLASH_KPAD + 64*FLASH_VPAD) * (int)sizeof(unsigned))

__global__ __launch_bounds__(256) void flash_kernel(
    const unsigned* __restrict__ q, const unsigned* __restrict__ k,
    const float* __restrict__ v, unsigned* __restrict__ ctxs)
{
    extern __shared__ unsigned dsm[];
    unsigned (*Ks)[FLASH_KPAD] = reinterpret_cast<unsigned(*)[FLASH_KPAD]>(dsm);
    unsigned (*Vs)[FLASH_VPAD] = reinterpret_cast<unsigned(*)[FLASH_VPAD]>(dsm + 32*FLASH_KPAD);

    const int it = (int)(gridDim.x - 1 - blockIdx.x);
    const int bh = blockIdx.y, b = bh >> 3, h = bh & 7;
    const unsigned* qb = q + (size_t)b*SS*HPH + h*32;
    const unsigned* kb = k + (size_t)b*SS*HPH + h*32;
    const float*    vb = v + (size_t)b*SS*HDIM + h*DH;
    unsigned*       cb = ctxs + (size_t)b*SS*HPH + h*32;

    const int tid  = threadIdx.x, lane = tid & 31, warp = tid >> 5;
    const int g    = lane >> 2,  tg   = lane & 3;
    const int i0   = it * 128;
    const int rowg = i0 + warp*16 + g;

    unsigned qf[4][4];
    {
        const unsigned* qrg = qb + (size_t)rowg*HPH;
        const unsigned* qr8 = qrg + 8*HPH;
        #pragma unroll
        for (int kk = 0; kk < 4; kk++) {
            qf[kk][0] = qrg[kk*8 + tg];
            qf[kk][1] = qr8[kk*8 + tg];
            qf[kk][2] = qrg[kk*8 + tg + 4];
            qf[kk][3] = qr8[kk*8 + tg + 4];
        }
    }

    float m0 = -1e30f, m1 = -1e30f, l0 = 0.f, l1 = 0.f;
    float o[8][4];
    #pragma unroll
    for (int nf = 0; nf < 8; nf++)
        #pragma unroll
        for (int l = 0; l < 4; l++) o[nf][l] = 0.f;

    const int kjr = tid >> 1, kcb = (tid & 1)*16;
    const int vjp = tid >> 2, vcb = (tid & 3)*16;

    for (int jt = 0; jt <= it; jt++) {
        const int j0 = jt * 128;
        {
            const unsigned* krow = kb + (size_t)(j0 + kjr)*HPH + kcb;
            #pragma unroll
            for (int u = 0; u < 4; u++) {
                uint4 f = ((const uint4*)krow)[u];
                Ks[kcb + 4*u + 0][kjr] = f.x;
                Ks[kcb + 4*u + 1][kjr] = f.y;
                Ks[kcb + 4*u + 2][kjr] = f.z;
                Ks[kcb + 4*u + 3][kjr] = f.w;
            }
        }
        {
            const float* vr0 = vb + (size_t)(j0 + 2*vjp)*HDIM + vcb;
            const float* vr1 = vr0 + HDIM;
            #pragma unroll
            for (int u = 0; u < 4; u++) {
                float4 f0 = *(const float4*)(vr0 + u*4);
                float4 f1 = *(const float4*)(vr1 + u*4);
                Vs[vjp][vcb + u*4 + 0] = pack2h(f0.x, f1.x);
                Vs[vjp][vcb + u*4 + 1] = pack2h(f0.y, f1.y);
                Vs[vjp][vcb + u*4 + 2] = pack2h(f0.z, f1.z);
                Vs[vjp][vcb + u*4 + 3] = pack2h(f0.w, f1.w);
            }
        }
        __syncthreads();

        float s[16][4];
        #pragma unroll
        for (int jf = 0; jf < 16; jf++)
            #pragma unroll
            for (int l = 0; l < 4; l++) s[jf][l] = 0.f;

        #pragma unroll
        for (int kk = 0; kk < 4; kk++) {
            unsigned a0 = qf[kk][0], a1 = qf[kk][1], a2 = qf[kk][2], a3 = qf[kk][3];
            #pragma unroll
            for (int jf = 0; jf < 16; jf++) {
                unsigned b0 = Ks[kk*8 + tg][jf*8 + g];
                unsigned b1 = Ks[kk*8 + tg + 4][jf*8 + g];
                mma16(s[jf], a0, a1, a2, a3, b0, b1);
            }
        }

        if (jt == it) {
            const int r0 = warp*16 + g, r1 = r0 + 8;
            #pragma unroll
            for (int jf = 0; jf < 16; jf++) {
                int c0 = jf*8 + 2*tg;
                if (c0     > r0) s[jf][0] = -1e30f;
                if (c0 + 1 > r0) s[jf][1] = -1e30f;
                if (c0     > r1) s[jf][2] = -1e30f;
                if (c0 + 1 > r1) s[jf][3] = -1e30f;
            }
        }

        float tm0 = -1e30f, tm1 = -1e30f;
        #pragma unroll
        for (int jf = 0; jf < 16; jf++) {
            tm0 = fmaxf(tm0, fmaxf(s[jf][0], s[jf][1]));
            tm1 = fmaxf(tm1, fmaxf(s[jf][2], s[jf][3]));
        }
        tm0 = fmaxf(tm0, __shfl_xor_sync(0xffffffffu, tm0, 1));
        tm0 = fmaxf(tm0, __shfl_xor_sync(0xffffffffu, tm0, 2));
        tm1 = fmaxf(tm1, __shfl_xor_sync(0xffffffffu, tm1, 1));
        tm1 = fmaxf(tm1, __shfl_xor_sync(0xffffffffu, tm1, 2));

        float nm0 = fmaxf(m0, tm0), nm1 = fmaxf(m1, tm1);
        float al0 = __expf(m0 - nm0), al1 = __expf(m1 - nm1);
        m0 = nm0; m1 = nm1;

        float rs0 = 0.f, rs1 = 0.f;
        #pragma unroll
        for (int jf = 0; jf < 16; jf++) {
            s[jf][0] = __expf(s[jf][0] - nm0);
            s[jf][1] = __expf(s[jf][1] - nm0);
            s[jf][2] = __expf(s[jf][2] - nm1);
            s[jf][3] = __expf(s[jf][3] - nm1);
            rs0 += s[jf][0] + s[jf][1];
            rs1 += s[jf][2] + s[jf][3];
        }
        rs0 += __shfl_xor_sync(0xffffffffu, rs0, 1);
        rs0 += __shfl_xor_sync(0xffffffffu, rs0, 2);
        rs1 += __shfl_xor_sync(0xffffffffu, rs1, 1);
        rs1 += __shfl_xor_sync(0xffffffffu, rs1, 2);
        l0 = l0*al0 + rs0;
        l1 = l1*al1 + rs1;

        #pragma unroll
        for (int nf = 0; nf < 8; nf++) {
            o[nf][0] *= al0; o[nf][1] *= al0;
            o[nf][2] *= al1; o[nf][3] *= al1;
        }

        #pragma unroll
        for (int kk = 0; kk < 8; kk++) {
            unsigned A0 = pack2h(s[2*kk][0],   s[2*kk][1]);
            unsigned A1 = pack2h(s[2*kk][2],   s[2*kk][3]);
            unsigned A2 = pack2h(s[2*kk+1][0], s[2*kk+1][1]);
            unsigned A3 = pack2h(s[2*kk+1][2], s[2*kk+1][3]);
            #pragma unroll
            for (int nf = 0; nf < 8; nf++) {
                unsigned b0 = Vs[kk*8 + tg][nf*8 + g];
                unsigned b1 = Vs[kk*8 + tg + 4][nf*8 + g];
                mma16(o[nf], A0, A1, A2, A3, b0, b1);
            }
        }
        __syncthreads();
    }

    float inv0 = 1.0f / l0, inv1 = 1.0f / l1;
    unsigned* crow0 = cb + (size_t)rowg*HPH;
    unsigned* crow1 = crow0 + 8*HPH;
    #pragma unroll
    for (int nf = 0; nf < 8; nf++) {
        crow0[nf*4 + tg] = pack2h(o[nf][0]*inv0, o[nf][1]*inv0);
        crow1[nf*4 + tg] = pack2h(o[nf][2]*inv1, o[nf][3]*inv1);
    }
}

// ---------- layernorm over (p0 + p1 + bias + res): warp-per-row ---------------
__global__ __launch_bounds__(256) void ln_sum_kernel(
    const float* __restrict__ p0, const float* __restrict__ p1,
    const float* __restrict__ bias, const float* __restrict__ res,
    const float* __restrict__ g, const float* __restrict__ b,
    float* __restrict__ out, unsigned* __restrict__ outs)
{
    int row  = blockIdx.x * 8 + (threadIdx.x >> 5);
    int lane = threadIdx.x & 31;
    const float* p0r = p0 + (size_t)row * HDIM;
    const float* p1r = p1 + (size_t)row * HDIM;
    const float* rr  = res + (size_t)row * HDIM;

    float4 xv[4];
    float sum = 0.f;
    #pragma unroll
    for (int i = 0; i < 4; i++) {
        int c = lane*4 + i*128;
        float4 a = *(const float4*)(p0r + c);
        float4 d = *(const float4*)(p1r + c);
        float4 e = *(const float4*)(bias + c);
        float4 f = *(const float4*)(rr + c);
        xv[i].x = a.x + d.x + e.x + f.x;
        xv[i].y = a.y + d.y + e.y + f.y;
        xv[i].z = a.z + d.z + e.z + f.z;
        xv[i].w = a.w + d.w + e.w + f.w;
        sum += (xv[i].x + xv[i].y) + (xv[i].z + xv[i].w);
    }
    #pragma unroll
    for (int o = 16; o; o >>= 1) sum += __shfl_xor_sync(0xffffffffu, sum, o);
    float m = sum * (1.0f / HDIM);

    float ssq = 0.f;
    #pragma unroll
    for (int i = 0; i < 4; i++) {
        xv[i].x -= m; xv[i].y -= m; xv[i].z -= m; xv[i].w -= m;
        ssq += xv[i].x*xv[i].x + xv[i].y*xv[i].y + xv[i].z*xv[i].z + xv[i].w*xv[i].w;
    }
    #pragma unroll
    for (int o = 16; o; o >>= 1) ssq += __shfl_xor_sync(0xffffffffu, ssq, o);
    float rstd = rsqrtf(ssq * (1.0f / HDIM) + 1e-5f);

    float* outr = out + (size_t)row * HDIM;
    unsigned* outsr = outs + (size_t)row * HPH;
    #pragma unroll
    for (int i = 0; i < 4; i++) {
        int c = lane*4 + i*128;
        float4 gv = *(const float4*)(g + c);
        float4 bv = *(const float4*)(b + c);
        float4 ov;
        ov.x = xv[i].x * rstd * gv.x + bv.x;
        ov.y = xv[i].y * rstd * gv.y + bv.y;
        ov.z = xv[i].z * rstd * gv.z + bv.z;
        ov.w = xv[i].w * rstd * gv.w + bv.w;
        *(float4*)(outr + c) = ov;
        outsr[(c >> 1)    ] = pack2h(ov.x, ov.y);
        outsr[(c >> 1) + 1] = pack2h(ov.z, ov.w);
    }
}

// ---------------- final projection ----------------
__global__ __launch_bounds__(256) void final_kernel(
    const float* __restrict__ h, const float* __restrict__ Wp,
    const float* __restrict__ bp, float* __restrict__ out)
{
    int bt = blockIdx.x;
    int b = bt / TT, t = bt % TT;
    const float* row = h + ((size_t)b*SS + 3*t + 1) * HDIM;
    __shared__ float sRow[HDIM];
    __shared__ float part[8][ADIM];
    int tid = threadIdx.x;
    sRow[tid] = row[tid];
    sRow[tid + 256] = row[tid + 256];
    __syncthreads();
    int c = tid & 31, g = tid >> 5;
    float a = 0.f;
    for (int k = g*64; k < (g+1)*64; k++) a = fmaf(sRow[k], Wp[(size_t)k*ADIM + c], a);
    part[g][c] = a;
    __syncthreads();
    if (tid < ADIM) {
        float s = bp[tid];
        #pragma unroll
        for (int g2 = 0; g2 < 8; g2++) s += part[g2][tid];
        out[(size_t)bt*ADIM + tid] = s;
    }
}

// ---------------- driver ----------------
extern "C" void kernel_launch(void* const* d_in, const int* in_sizes, int n_in,
                              void* d_out, int out_size)
{
    const int*   timesteps = (const int*)  d_in[0];
    const float* state_0   = (const float*)d_in[1];
    const float* state_1   = (const float*)d_in[2];
    const float* actions   = (const float*)d_in[3];
    const float* time_emb  = (const float*)d_in[4];
    const float* Ws  = (const float*)d_in[5];
    const float* bs  = (const float*)d_in[6];
    const float* Wa  = (const float*)d_in[7];
    const float* ba  = (const float*)d_in[8];
    const float* Wq  = (const float*)d_in[9];
    const float* bq  = (const float*)d_in[10];
    const float* Wk  = (const float*)d_in[11];
    const float* bk  = (const float*)d_in[12];
    const float* Wv  = (const float*)d_in[13];
    const float* bv  = (const float*)d_in[14];
    const float* Wo  = (const float*)d_in[15];
    const float* bo  = (const float*)d_in[16];
    const float* W1  = (const float*)d_in[17];
    const float* b1  = (const float*)d_in[18];
    const float* W2  = (const float*)d_in[19];
    const float* b2  = (const float*)d_in[20];
    const float* ln1_g = (const float*)d_in[21];
    const float* ln1_b = (const float*)d_in[22];
    const float* ln2_g = (const float*)d_in[23];
    const float* ln2_b = (const float*)d_in[24];
    const float* eln_g = (const float*)d_in[25];
    const float* eln_b = (const float*)d_in[26];
    const float* Wp  = (const float*)d_in[27];
    const float* bp  = (const float*)d_in[28];

    float *h, *v, *p0, *p1, *ln1o;
    unsigned *hs, *qs, *ksp, *ctxs, *ln1s, *mlps, *ws;
    cudaGetSymbolAddress((void**)&h,    g_h);
    cudaGetSymbolAddress((void**)&v,    g_v);
    cudaGetSymbolAddress((void**)&p0,   g_p0);
    cudaGetSymbolAddress((void**)&p1,   g_p1);
    cudaGetSymbolAddress((void**)&ln1o, g_ln1);
    cudaGetSymbolAddress((void**)&hs,   g_hs);
    cudaGetSymbolAddress((void**)&qs,   g_qs);
    cudaGetSymbolAddress((void**)&ksp,  g_ksp);
    cudaGetSymbolAddress((void**)&ctxs, g_ctxs);
    cudaGetSymbolAddress((void**)&ln1s, g_ln1s);
    cudaGetSymbolAddress((void**)&mlps, g_mlps);
    cudaGetSymbolAddress((void**)&ws,   g_ws);

    cudaFuncSetAttribute(flash_kernel,
                         cudaFuncAttributeMaxDynamicSharedMemorySize, FLASH_SMEM);
    cudaFuncSetAttribute(tgemm_kernel<128>,
                         cudaFuncAttributeMaxDynamicSharedMemorySize, SM128);
    cudaFuncSetAttribute(tgemm_splitk_kernel,
                         cudaFuncAttributeMaxDynamicSharedMemorySize, SM64_3);
    cudaFuncSetAttribute(qkv_kernel,
                         cudaFuncAttributeMaxDynamicSharedMemorySize, SM128);

    wsplit_kernel<<<dim3(HDIM/256, NBLK*HDIM/2), 256>>>(Wq, ws + WQ0, HDIM);
    wsplit_kernel<<<dim3(HDIM/256, NBLK*HDIM/2), 256>>>(Wk, ws + WK0, HDIM);
    wsplit_kernel<<<dim3(HDIM/256, NBLK*HDIM/2), 256>>>(Wv, ws + WV0, HDIM);
    wsplit_kernel<<<dim3(HDIM/256, NBLK*HDIM/2), 256>>>(Wo, ws + WO0, HDIM);
    wsplit_kernel<<<dim3(DFF/256,  NBLK*HDIM/2), 256>>>(W1, ws + W10, DFF);
    wsplit_kernel<<<dim3(HDIM/256, NBLK*DFF/2),  256>>>(W2, ws + W20, HDIM);

    embed_kernel<<<BB*SS, 256>>>(timesteps, state_0, state_1, actions, time_emb,
                                 Ws, bs, Wa, ba, eln_g, eln_b, h, hs);

    dim3 gQKV(HDIM/128, MROWS/128, 3);   // (4, 48, 3)
    dim3 gSK (HDIM/64,  MROWS/128, 2);   // (8, 48, 2)
    dim3 gF  (DFF /128, MROWS/128);      // (16, 48)
    dim3 gFl (SS/128, BB*NH);            // (12, 32)

    for (int blk = 0; blk < NBLK; blk++) {
        const unsigned* wqs = ws + WQ0 + (size_t)blk*131072;
        const unsigned* wks = ws + WK0 + (size_t)blk*131072;
        const unsigned* wvs = ws + WV0 + (size_t)blk*131072;
        const unsigned* wos = ws + WO0 + (size_t)blk*131072;
        const unsigned* w1s = ws + W10 + (size_t)blk*524288;
        const unsigned* w2s = ws + W20 + (size_t)blk*524288;
        const float* bq_ = bq + (size_t)blk*HDIM;
        const float* bk_ = bk + (size_t)blk*HDIM;
        const float* bv_ = bv + (size_t)blk*HDIM;
        const float* bo_ = bo + (size_t)blk*HDIM;
        const float* b1_ = b1 + (size_t)blk*DFF;
        const float* b2_ = b2 + (size_t)blk*HDIM;
        const float* g1_ = ln1_g + (size_t)blk*HDIM;
        const float* e1_ = ln1_b + (size_t)blk*HDIM;
        const float* g2_ = ln2_g + (size_t)blk*HDIM;
        const float* e2_ = ln2_b + (size_t)blk*HDIM;

        qkv_kernel<<<gQKV, 256, SM128>>>(hs, wqs, wks, wvs, bq_, bk_, bv_, qs, ksp, v);

        flash_kernel<<<gFl, 256, FLASH_SMEM>>>(qs, ksp, v, ctxs);

        tgemm_splitk_kernel<<<gSK, 256, SM64_3>>>(ctxs, wos, p0, p1, HDIM, HDIM);
        ln_sum_kernel<<<MROWS/8, 256>>>(p0, p1, bo_, h, g1_, e1_, ln1o, ln1s);
        tgemm_kernel<128><<<gF, 256, SM128>>>(ln1s, w1s, b1_, nullptr, mlps,
                                              MROWS, DFF, HDIM, EP_GELU_PACK);
        tgemm_splitk_kernel<<<gSK, 256, SM64_3>>>(mlps, w2s, p0, p1, HDIM, DFF);
        ln_sum_kernel<<<MROWS/8, 256>>>(p0, p1, b2_, ln1o, g2_, e2_, h, hs);
    }

    final_kernel<<<BB*TT, 256>>>(h, Wp, bp, (float*)d_out);
}